// round 5
// baseline (speedup 1.0000x reference)
#include <cuda_runtime.h>
#include <math.h>

// Problem constants
static const int BB   = 16;
static const int CC   = 256;
static const int SS   = 1024;   // 32*32
static const int NH   = 8;
static const int DKk  = 32;
static const int GR   = 8;
static const int TDIM = 512;
static const int CDIM = 128;
static const int INDIM = 640;   // TDIM + CDIM
static const int TWOC = 512;

// Device scratch (allocations are forbidden; globals are allowed)
__device__ float g_params[BB * TWOC];       // adaLN gamma/beta, (b, 2C)
__device__ float g_mean[BB * GR];
__device__ float g_rstd[BB * GR];
__device__ float g_xn[BB * SS * CC];        // normalized input, (b, s, c)
__device__ float g_q[BB * NH * SS * DKk];   // (b,h,s,d)
__device__ float g_k[BB * NH * SS * DKk];
__device__ float g_v[BB * NH * SS * DKk];
__device__ float g_att[BB * SS * CC];       // attention output, (b, s, c)

// ---------------------------------------------------------------------------
// K1: adaLN projection: params[b, :] = silu(concat(t_emb, cond)) @ proj_w^T + proj_b
// grid = 16, block = 640
// ---------------------------------------------------------------------------
__global__ void k_adaln(const float* __restrict__ t_emb,
                        const float* __restrict__ c_emb,
                        const float* __restrict__ pw,
                        const float* __restrict__ pb) {
    __shared__ float sin_[INDIM];
    int b = blockIdx.x;
    int t = threadIdx.x;            // 0..639
    float v = (t < TDIM) ? t_emb[b * TDIM + t] : c_emb[b * CDIM + (t - TDIM)];
    sin_[t] = v / (1.0f + expf(-v));
    __syncthreads();
    if (t < TWOC) {
        const float* wr = pw + t * INDIM;
        float acc = pb[t];
#pragma unroll 8
        for (int i = 0; i < INDIM; i++) acc += sin_[i] * wr[i];
        g_params[b * TWOC + t] = acc;
    }
}

// ---------------------------------------------------------------------------
// K2: GroupNorm statistics. One block per (b, g): reduce 32*1024 = 32768 floats
// (channels of a group are contiguous in x). grid = 128, block = 256
// ---------------------------------------------------------------------------
__global__ void k_gnstat(const float* __restrict__ x) {
    int bg = blockIdx.x;  // b*8 + g  ->  linear offset bg * 32768 floats
    const float4* p = (const float4*)(x + (size_t)bg * 32768);
    float s = 0.0f, ss = 0.0f;
    for (int i = threadIdx.x; i < 8192; i += 256) {
        float4 v = p[i];
        s  += v.x + v.y + v.z + v.w;
        ss += v.x * v.x + v.y * v.y + v.z * v.z + v.w * v.w;
    }
#pragma unroll
    for (int o = 16; o; o >>= 1) {
        s  += __shfl_xor_sync(0xffffffffu, s, o);
        ss += __shfl_xor_sync(0xffffffffu, ss, o);
    }
    __shared__ float rs[8], rss[8];
    int w = threadIdx.x >> 5, l = threadIdx.x & 31;
    if (l == 0) { rs[w] = s; rss[w] = ss; }
    __syncthreads();
    if (threadIdx.x == 0) {
        float S = 0.0f, SSum = 0.0f;
#pragma unroll
        for (int i = 0; i < 8; i++) { S += rs[i]; SSum += rss[i]; }
        float m = S / 32768.0f;
        float var = SSum / 32768.0f - m * m;
        g_mean[bg] = m;
        g_rstd[bg] = rsqrtf(var + 1e-6f);
    }
}

// ---------------------------------------------------------------------------
// K3: apply GN + adaLN affine, transpose (b,c,s) -> (b,s,c).
// grid = (32 s-tiles, 16 b), block = 256. smem tile [256 c][32 s].
// ---------------------------------------------------------------------------
__global__ void k_gnapply(const float* __restrict__ x,
                          const float* __restrict__ gw,
                          const float* __restrict__ gb) {
    __shared__ float tile[CC][33];
    int b = blockIdx.y;
    int s0 = blockIdx.x * 32;
    int t = threadIdx.x;
    int w = t >> 5, sl = t & 31;
#pragma unroll
    for (int k = 0; k < 32; k++) {
        int c = k * 8 + w;
        float v = x[(b * CC + c) * SS + s0 + sl];
        int g = c >> 5;
        float vn = (v - g_mean[b * GR + g]) * g_rstd[b * GR + g];
        vn = vn * gw[c] + gb[c];
        float gam = g_params[b * TWOC + c];
        float bet = g_params[b * TWOC + CC + c];
        tile[c][sl] = vn * (1.0f + gam) + bet;
    }
    __syncthreads();
#pragma unroll
    for (int k = 0; k < 32; k++) {
        g_xn[(b * SS + s0 + k) * CC + t] = tile[t][k];
    }
}

// ---------------------------------------------------------------------------
// K4: QKV GEMM. C[n, o] = xn[n, :] @ qkv_w[o, :] + qkv_b[o]
// M=16384, N=768, K=256. Tile 128x64x16, 256 thr, 8x4 microtile.
// Scatter q/k/v into (b,h,s,d). grid = (12, 128)
// ---------------------------------------------------------------------------
__global__ void __launch_bounds__(256) k_qkv(const float* __restrict__ w,
                                             const float* __restrict__ bias) {
    __shared__ float As[16][129];
    __shared__ float Bs[16][65];
    int m0 = blockIdx.y * 128;
    int o0 = blockIdx.x * 64;
    int tid = threadIdx.x;
    int tr = tid >> 4, tc = tid & 15;
    float acc[8][4];
#pragma unroll
    for (int r = 0; r < 8; r++)
#pragma unroll
        for (int c = 0; c < 4; c++) acc[r][c] = 0.0f;

    for (int k0 = 0; k0 < 256; k0 += 16) {
#pragma unroll
        for (int i = 0; i < 8; i++) {
            int row = tr + 16 * i;
            As[tc][row] = g_xn[(m0 + row) * 256 + k0 + tc];
        }
#pragma unroll
        for (int i = 0; i < 4; i++) {
            int o = tr + 16 * i;
            Bs[tc][o] = w[(o0 + o) * 256 + k0 + tc];
        }
        __syncthreads();
#pragma unroll
        for (int kk = 0; kk < 16; kk++) {
            float a[8], bv[4];
#pragma unroll
            for (int r = 0; r < 8; r++) a[r] = As[kk][tr + 16 * r];
#pragma unroll
            for (int c = 0; c < 4; c++) bv[c] = Bs[kk][tc + 16 * c];
#pragma unroll
            for (int r = 0; r < 8; r++)
#pragma unroll
                for (int c = 0; c < 4; c++) acc[r][c] += a[r] * bv[c];
        }
        __syncthreads();
    }

    int b = m0 >> 10;   // 1024 % 128 == 0 -> single b per block
#pragma unroll
    for (int r = 0; r < 8; r++) {
        int n = m0 + tr + 16 * r;
        int s = n & 1023;
#pragma unroll
        for (int c = 0; c < 4; c++) {
            int o = o0 + tc + 16 * c;
            float val = acc[r][c] + bias[o];
            int which = o >> 8;
            int h = (o >> 5) & 7;
            int d = o & 31;
            float* dst = (which == 0) ? g_q : ((which == 1) ? g_k : g_v);
            dst[((b * 8 + h) * 1024 + s) * 32 + d] = val;
        }
    }
}

// ---------------------------------------------------------------------------
// K5: attention with online softmax. block = (b*h, 64 q-rows), 256 thr (8 warps).
// Key tiles of 64. Warp w owns q-rows [8w, 8w+8); lane = d for O accumulator.
// grid = (128, 16)
// ---------------------------------------------------------------------------
__global__ void __launch_bounds__(256) k_attn() {
    __shared__ __align__(16) float qs[64][33];
    __shared__ __align__(16) float ks[64][33];
    __shared__ __align__(16) float vs[64][33];
    __shared__ __align__(16) float sc[64][68];

    int bh = blockIdx.x;                 // 0..127
    int m0 = blockIdx.y * 64;
    int tid = threadIdx.x;
    int w = tid >> 5, lane = tid & 31;
    int tr = tid >> 4, tc = tid & 15;
    const float scale = 0.17677669529663687f;   // 1/sqrt(32)
    int base = bh * (1024 * 32);

    // Load Q tile (pre-scaled)
#pragma unroll
    for (int i = 0; i < 8; i++) {
        int idx = i * 256 + tid;
        int r = idx >> 5, d = idx & 31;
        qs[r][d] = g_q[base + (m0 + r) * 32 + d] * scale;
    }

    float m_i[8], l_i[8], o_i[8];
#pragma unroll
    for (int i = 0; i < 8; i++) { m_i[i] = -1e30f; l_i[i] = 0.0f; o_i[i] = 0.0f; }

    for (int j0 = 0; j0 < 1024; j0 += 64) {
        __syncthreads();   // previous tile's phase C done before overwrite
#pragma unroll
        for (int i = 0; i < 8; i++) {
            int idx = i * 256 + tid;
            int r = idx >> 5, d = idx & 31;
            ks[r][d] = g_k[base + (j0 + r) * 32 + d];
            vs[r][d] = g_v[base + (j0 + r) * 32 + d];
        }
        __syncthreads();

        // --- Phase A: scores 64x64 (4x4 microtile; warp covers its own 8 rows)
        float accA[4][4];
#pragma unroll
        for (int r = 0; r < 4; r++)
#pragma unroll
            for (int c = 0; c < 4; c++) accA[r][c] = 0.0f;
#pragma unroll
        for (int d = 0; d < 32; d++) {
            float a[4], bq[4];
#pragma unroll
            for (int r = 0; r < 4; r++) a[r] = qs[tr * 4 + r][d];
#pragma unroll
            for (int c = 0; c < 4; c++) bq[c] = ks[tc + 16 * c][d];
#pragma unroll
            for (int r = 0; r < 4; r++)
#pragma unroll
                for (int c = 0; c < 4; c++) accA[r][c] += a[r] * bq[c];
        }
#pragma unroll
        for (int r = 0; r < 4; r++)
#pragma unroll
            for (int c = 0; c < 4; c++)
                sc[tr * 4 + r][tc + 16 * c] = accA[r][c];
        __syncwarp();

        // --- Phase B: online softmax per row (warp-local rows)
#pragma unroll
        for (int i = 0; i < 8; i++) {
            int r = w * 8 + i;
            float x1 = sc[r][lane];
            float x2 = sc[r][lane + 32];
            float t = fmaxf(x1, x2);
#pragma unroll
            for (int off = 16; off; off >>= 1)
                t = fmaxf(t, __shfl_xor_sync(0xffffffffu, t, off));
            float mn = fmaxf(m_i[i], t);
            float corr = __expf(m_i[i] - mn);
            float p1 = __expf(x1 - mn);
            float p2 = __expf(x2 - mn);
            sc[r][lane] = p1;
            sc[r][lane + 32] = p2;
            float ps = p1 + p2;
#pragma unroll
            for (int off = 16; off; off >>= 1)
                ps += __shfl_xor_sync(0xffffffffu, ps, off);
            l_i[i] = l_i[i] * corr + ps;
            m_i[i] = mn;
            o_i[i] *= corr;
        }
        __syncwarp();

        // --- Phase C: O += P @ V  (lane = d)
#pragma unroll
        for (int jg = 0; jg < 16; jg++) {
            float v0 = vs[jg * 4 + 0][lane];
            float v1 = vs[jg * 4 + 1][lane];
            float v2 = vs[jg * 4 + 2][lane];
            float v3 = vs[jg * 4 + 3][lane];
#pragma unroll
            for (int i = 0; i < 8; i++) {
                float4 p = *(const float4*)(&sc[w * 8 + i][jg * 4]);
                o_i[i] += p.x * v0 + p.y * v1 + p.z * v2 + p.w * v3;
            }
        }
    }

    // Epilogue: normalize and write (b, s, c = h*32 + d)
    int b = bh >> 3, h = bh & 7;
#pragma unroll
    for (int i = 0; i < 8; i++) {
        int s = m0 + w * 8 + i;
        g_att[(b * 1024 + s) * 256 + h * 32 + lane] = o_i[i] / l_i[i];
    }
}

// ---------------------------------------------------------------------------
// K6: output projection + bias + residual, store transposed to (b, c, s).
// M=16384, N=256, K=256. Tile 128x64x16, smem-staged transpose store.
// grid = (4, 128)
// ---------------------------------------------------------------------------
__global__ void __launch_bounds__(256) k_oproj(const float* __restrict__ w,
                                               const float* __restrict__ bias,
                                               const float* __restrict__ x,
                                               float* __restrict__ out) {
    __shared__ float As[16][129];
    __shared__ float Bs[16][65];
    __shared__ float ot[128][65];
    int m0 = blockIdx.y * 128;
    int o0 = blockIdx.x * 64;
    int tid = threadIdx.x;
    int tr = tid >> 4, tc = tid & 15;
    float acc[8][4];
#pragma unroll
    for (int r = 0; r < 8; r++)
#pragma unroll
        for (int c = 0; c < 4; c++) acc[r][c] = 0.0f;

    for (int k0 = 0; k0 < 256; k0 += 16) {
#pragma unroll
        for (int i = 0; i < 8; i++) {
            int row = tr + 16 * i;
            As[tc][row] = g_att[(m0 + row) * 256 + k0 + tc];
        }
#pragma unroll
        for (int i = 0; i < 4; i++) {
            int o = tr + 16 * i;
            Bs[tc][o] = w[(o0 + o) * 256 + k0 + tc];
        }
        __syncthreads();
#pragma unroll
        for (int kk = 0; kk < 16; kk++) {
            float a[8], bv[4];
#pragma unroll
            for (int r = 0; r < 8; r++) a[r] = As[kk][tr + 16 * r];
#pragma unroll
            for (int c = 0; c < 4; c++) bv[c] = Bs[kk][tc + 16 * c];
#pragma unroll
            for (int r = 0; r < 8; r++)
#pragma unroll
                for (int c = 0; c < 4; c++) acc[r][c] += a[r] * bv[c];
        }
        __syncthreads();
    }

    // stage to smem with bias
#pragma unroll
    for (int r = 0; r < 8; r++)
#pragma unroll
        for (int c = 0; c < 4; c++)
            ot[tr + 16 * r][tc + 16 * c] = acc[r][c] + bias[o0 + tc + 16 * c];
    __syncthreads();

    // coalesced transposed store with residual
    int b = m0 >> 10;
    int sbase = m0 & 1023;
#pragma unroll
    for (int k = 0; k < 32; k++) {
        int cl = k * 2 + (tid >> 7);    // 0..63
        int nl = tid & 127;             // 0..127
        int idx = (b * 256 + o0 + cl) * 1024 + sbase + nl;
        out[idx] = ot[nl][cl] + x[idx];
    }
}

// ---------------------------------------------------------------------------
extern "C" void kernel_launch(void* const* d_in, const int* in_sizes, int n_in,
                              void* d_out, int out_size) {
    const float* x      = (const float*)d_in[0];
    const float* t_emb  = (const float*)d_in[1];
    const float* c_emb  = (const float*)d_in[2];
    const float* gn_w   = (const float*)d_in[3];
    const float* gn_b   = (const float*)d_in[4];
    const float* proj_w = (const float*)d_in[5];
    const float* proj_b = (const float*)d_in[6];
    const float* qkv_w  = (const float*)d_in[7];
    const float* qkv_b  = (const float*)d_in[8];
    const float* out_w  = (const float*)d_in[9];
    const float* out_b  = (const float*)d_in[10];
    float* out = (float*)d_out;

    k_adaln<<<16, 640>>>(t_emb, c_emb, proj_w, proj_b);
    k_gnstat<<<128, 256>>>(x);
    k_gnapply<<<dim3(32, 16), 256>>>(x, gn_w, gn_b);
    k_qkv<<<dim3(12, 128), 256>>>(qkv_w, qkv_b);
    k_attn<<<dim3(128, 16), 256>>>();
    k_oproj<<<dim3(4, 128), 256>>>(out_w, out_b, x, out);
}

// round 6
// speedup vs baseline: 1.1483x; 1.1483x over previous
#include <cuda_runtime.h>
#include <math.h>

// Problem constants
static const int BB   = 16;
static const int CC   = 256;
static const int SS   = 1024;   // 32*32
static const int NH   = 8;
static const int DKk  = 32;
static const int GR   = 8;
static const int TDIM = 512;
static const int CDIM = 128;
static const int INDIM = 640;   // TDIM + CDIM
static const int TWOC = 512;

// Device scratch (allocations are forbidden; globals are allowed)
__device__ float g_params[BB * TWOC];       // adaLN gamma/beta, (b, 2C)
__device__ float g_mean[BB * GR];
__device__ float g_rstd[BB * GR];
__device__ float g_xn[BB * SS * CC];        // normalized input, (b, s, c)
__device__ float g_q[BB * NH * SS * DKk];   // (b,h,s,d)
__device__ float g_k[BB * NH * SS * DKk];
__device__ float g_v[BB * NH * SS * DKk];
__device__ float g_att[BB * SS * CC];       // attention output, (b, s, c)

// ---------------------------------------------------------------------------
// K1: adaLN projection: params[b,:] = silu(concat(t_emb, cond)) @ proj_w^T + pb
// grid = 16, block = 640
// ---------------------------------------------------------------------------
__global__ void k_adaln(const float* __restrict__ t_emb,
                        const float* __restrict__ c_emb,
                        const float* __restrict__ pw,
                        const float* __restrict__ pb) {
    __shared__ float sin_[INDIM];
    int b = blockIdx.x;
    int t = threadIdx.x;            // 0..639
    float v = (t < TDIM) ? t_emb[b * TDIM + t] : c_emb[b * CDIM + (t - TDIM)];
    sin_[t] = v / (1.0f + expf(-v));
    __syncthreads();
    if (t < TWOC) {
        const float* wr = pw + t * INDIM;
        float acc = pb[t];
#pragma unroll 8
        for (int i = 0; i < INDIM; i++) acc += sin_[i] * wr[i];
        g_params[b * TWOC + t] = acc;
    }
}

// ---------------------------------------------------------------------------
// K2: GroupNorm statistics. One block per (b, g). grid = 128, block = 256
// ---------------------------------------------------------------------------
__global__ void k_gnstat(const float* __restrict__ x) {
    int bg = blockIdx.x;
    const float4* p = (const float4*)(x + (size_t)bg * 32768);
    float s = 0.0f, ss = 0.0f;
    for (int i = threadIdx.x; i < 8192; i += 256) {
        float4 v = p[i];
        s  += v.x + v.y + v.z + v.w;
        ss += v.x * v.x + v.y * v.y + v.z * v.z + v.w * v.w;
    }
#pragma unroll
    for (int o = 16; o; o >>= 1) {
        s  += __shfl_xor_sync(0xffffffffu, s, o);
        ss += __shfl_xor_sync(0xffffffffu, ss, o);
    }
    __shared__ float rs[8], rss[8];
    int w = threadIdx.x >> 5, l = threadIdx.x & 31;
    if (l == 0) { rs[w] = s; rss[w] = ss; }
    __syncthreads();
    if (threadIdx.x == 0) {
        float S = 0.0f, SSum = 0.0f;
#pragma unroll
        for (int i = 0; i < 8; i++) { S += rs[i]; SSum += rss[i]; }
        float m = S / 32768.0f;
        float var = SSum / 32768.0f - m * m;
        g_mean[bg] = m;
        g_rstd[bg] = rsqrtf(var + 1e-6f);
    }
}

// ---------------------------------------------------------------------------
// K3: apply GN + adaLN affine, transpose (b,c,s) -> (b,s,c).
// grid = (32 s-tiles, 16 b), block = 256.
// ---------------------------------------------------------------------------
__global__ void k_gnapply(const float* __restrict__ x,
                          const float* __restrict__ gw,
                          const float* __restrict__ gb) {
    __shared__ float tile[CC][33];
    int b = blockIdx.y;
    int s0 = blockIdx.x * 32;
    int t = threadIdx.x;
    int w = t >> 5, sl = t & 31;
#pragma unroll
    for (int k = 0; k < 32; k++) {
        int c = k * 8 + w;
        float v = x[(b * CC + c) * SS + s0 + sl];
        int g = c >> 5;
        float vn = (v - g_mean[b * GR + g]) * g_rstd[b * GR + g];
        vn = vn * gw[c] + gb[c];
        float gam = g_params[b * TWOC + c];
        float bet = g_params[b * TWOC + CC + c];
        tile[c][sl] = vn * (1.0f + gam) + bet;
    }
    __syncthreads();
#pragma unroll
    for (int k = 0; k < 32; k++) {
        g_xn[(b * SS + s0 + k) * CC + t] = tile[t][k];
    }
}

// ---------------------------------------------------------------------------
// K4: QKV GEMM. C[n,o] = xn[n,:] @ qkv_w[o,:] + qkv_b[o]
// M=16384, N=768, K=256. Tile 128x128x16, 256 thr, 8x8 microtile, float4 LDS.
// grid = (6, 128)
// ---------------------------------------------------------------------------
__global__ void __launch_bounds__(256) k_qkv(const float* __restrict__ w,
                                             const float* __restrict__ bias) {
    __shared__ float As[16][132];
    __shared__ float Bs[16][132];
    int m0 = blockIdx.y * 128;
    int o0 = blockIdx.x * 128;
    int tid = threadIdx.x;
    int tr = tid >> 4, tc = tid & 15;
    float acc[8][8];
#pragma unroll
    for (int r = 0; r < 8; r++)
#pragma unroll
        for (int c = 0; c < 8; c++) acc[r][c] = 0.0f;

    for (int k0 = 0; k0 < 256; k0 += 16) {
#pragma unroll
        for (int i = 0; i < 2; i++) {
            int idx = tid + i * 256;          // 0..511
            int row = idx >> 2, kq = idx & 3;
            float4 v = *(const float4*)&g_xn[(m0 + row) * 256 + k0 + kq * 4];
            As[kq * 4 + 0][row] = v.x;
            As[kq * 4 + 1][row] = v.y;
            As[kq * 4 + 2][row] = v.z;
            As[kq * 4 + 3][row] = v.w;
        }
#pragma unroll
        for (int i = 0; i < 2; i++) {
            int idx = tid + i * 256;
            int row = idx >> 2, kq = idx & 3;
            float4 v = *(const float4*)&w[(o0 + row) * 256 + k0 + kq * 4];
            Bs[kq * 4 + 0][row] = v.x;
            Bs[kq * 4 + 1][row] = v.y;
            Bs[kq * 4 + 2][row] = v.z;
            Bs[kq * 4 + 3][row] = v.w;
        }
        __syncthreads();
#pragma unroll
        for (int kk = 0; kk < 16; kk++) {
            float4 a0 = *(const float4*)&As[kk][tr * 4];
            float4 a1 = *(const float4*)&As[kk][tr * 4 + 64];
            float4 b0 = *(const float4*)&Bs[kk][tc * 4];
            float4 b1 = *(const float4*)&Bs[kk][tc * 4 + 64];
            float ar[8] = {a0.x, a0.y, a0.z, a0.w, a1.x, a1.y, a1.z, a1.w};
            float bc[8] = {b0.x, b0.y, b0.z, b0.w, b1.x, b1.y, b1.z, b1.w};
#pragma unroll
            for (int r = 0; r < 8; r++)
#pragma unroll
                for (int c = 0; c < 8; c++) acc[r][c] += ar[r] * bc[c];
        }
        __syncthreads();
    }

    float* dst; int obase;
    if (o0 < 256)      { dst = g_q; obase = o0; }
    else if (o0 < 512) { dst = g_k; obase = o0 - 256; }
    else               { dst = g_v; obase = o0 - 512; }
    int b = m0 >> 10;
#pragma unroll
    for (int rr = 0; rr < 2; rr++)
#pragma unroll
    for (int r = 0; r < 4; r++) {
        int s = (m0 + tr * 4 + rr * 64 + r) & 1023;
#pragma unroll
        for (int cc = 0; cc < 2; cc++) {
            int col = obase + tc * 4 + cc * 64;
            int h = col >> 5, d = col & 31;
            int bo = o0 + tc * 4 + cc * 64;
            float4 val;
            val.x = acc[rr * 4 + r][cc * 4 + 0] + bias[bo + 0];
            val.y = acc[rr * 4 + r][cc * 4 + 1] + bias[bo + 1];
            val.z = acc[rr * 4 + r][cc * 4 + 2] + bias[bo + 2];
            val.w = acc[rr * 4 + r][cc * 4 + 3] + bias[bo + 3];
            *(float4*)&dst[((b * 8 + h) * 1024 + s) * 32 + d] = val;
        }
    }
}

// ---------------------------------------------------------------------------
// K5: flash attention, 128 q-rows x 128 key tile, 256 thr (8 warps).
// Phase A: 8x8 microtile QK^T.  Phase B: per-warp online softmax (16 rows).
// Phase C: O += P@V with lane = d.  Dynamic smem (117KB).
// grid = (128 bh, 8 q-tiles)
// ---------------------------------------------------------------------------
static const int SMEM_ATTN = 29952 * 4;  // 119808 bytes

__global__ void __launch_bounds__(256, 1) k_attn() {
    extern __shared__ float sm[];
    float (*qT)[132] = (float(*)[132])(sm);           // 32 x 132 (d-major Q^T)
    float (*kT)[132] = (float(*)[132])(sm + 4224);    // 32 x 132 (d-major K^T)
    float (*vs)[36]  = (float(*)[36]) (sm + 8448);    // 128 x 36
    float (*sc)[132] = (float(*)[132])(sm + 13056);   // 128 x 132 scores/probs

    int bh = blockIdx.x;
    int m0 = blockIdx.y * 128;
    int tid = threadIdx.x;
    int w = tid >> 5, lane = tid & 31;
    int tr = tid >> 4, tc = tid & 15;
    const float scale = 0.17677669529663687f;   // 1/sqrt(32)
    int base = bh * (1024 * 32);

    // Load Q tile transposed, pre-scaled
#pragma unroll
    for (int i = 0; i < 4; i++) {
        int idx = tid + i * 256;         // 0..1023
        int row = idx >> 3, dq = idx & 7;
        float4 v = *(const float4*)&g_q[base + (m0 + row) * 32 + dq * 4];
        qT[dq * 4 + 0][row] = v.x * scale;
        qT[dq * 4 + 1][row] = v.y * scale;
        qT[dq * 4 + 2][row] = v.z * scale;
        qT[dq * 4 + 3][row] = v.w * scale;
    }

    float m_i[16], l_i[16], o_i[16];
#pragma unroll
    for (int i = 0; i < 16; i++) { m_i[i] = -1e30f; l_i[i] = 0.0f; o_i[i] = 0.0f; }

    for (int j0 = 0; j0 < 1024; j0 += 128) {
        __syncthreads();   // previous tile fully consumed
#pragma unroll
        for (int i = 0; i < 4; i++) {
            int idx = tid + i * 256;
            int row = idx >> 3, dq = idx & 7;
            float4 kv = *(const float4*)&g_k[base + (j0 + row) * 32 + dq * 4];
            kT[dq * 4 + 0][row] = kv.x;
            kT[dq * 4 + 1][row] = kv.y;
            kT[dq * 4 + 2][row] = kv.z;
            kT[dq * 4 + 3][row] = kv.w;
            float4 vv = *(const float4*)&g_v[base + (j0 + row) * 32 + dq * 4];
            *(float4*)&vs[row][dq * 4] = vv;
        }
        __syncthreads();

        // --- Phase A: scores 128x128, 8x8 microtile
        {
            float acc[8][8];
#pragma unroll
            for (int r = 0; r < 8; r++)
#pragma unroll
                for (int c = 0; c < 8; c++) acc[r][c] = 0.0f;
#pragma unroll
            for (int d = 0; d < 32; d++) {
                float4 a0 = *(const float4*)&qT[d][tr * 4];
                float4 a1 = *(const float4*)&qT[d][tr * 4 + 64];
                float4 b0 = *(const float4*)&kT[d][tc * 4];
                float4 b1 = *(const float4*)&kT[d][tc * 4 + 64];
                float ar[8] = {a0.x, a0.y, a0.z, a0.w, a1.x, a1.y, a1.z, a1.w};
                float bc[8] = {b0.x, b0.y, b0.z, b0.w, b1.x, b1.y, b1.z, b1.w};
#pragma unroll
                for (int r = 0; r < 8; r++)
#pragma unroll
                    for (int c = 0; c < 8; c++) acc[r][c] += ar[r] * bc[c];
            }
#pragma unroll
            for (int rr = 0; rr < 2; rr++)
#pragma unroll
            for (int r = 0; r < 4; r++) {
                int qrow = tr * 4 + rr * 64 + r;
#pragma unroll
                for (int cc = 0; cc < 2; cc++) {
                    float4 val;
                    val.x = acc[rr * 4 + r][cc * 4 + 0];
                    val.y = acc[rr * 4 + r][cc * 4 + 1];
                    val.z = acc[rr * 4 + r][cc * 4 + 2];
                    val.w = acc[rr * 4 + r][cc * 4 + 3];
                    *(float4*)&sc[qrow][tc * 4 + cc * 64] = val;
                }
            }
        }
        __syncthreads();

        // --- Phase B: online softmax, warp w owns rows w*16..w*16+15
#pragma unroll
        for (int i = 0; i < 16; i++) {
            int r = w * 16 + i;
            float x0 = sc[r][lane];
            float x1 = sc[r][lane + 32];
            float x2 = sc[r][lane + 64];
            float x3 = sc[r][lane + 96];
            float t = fmaxf(fmaxf(x0, x1), fmaxf(x2, x3));
#pragma unroll
            for (int off = 16; off; off >>= 1)
                t = fmaxf(t, __shfl_xor_sync(0xffffffffu, t, off));
            float mn = fmaxf(m_i[i], t);
            float corr = __expf(m_i[i] - mn);
            float p0 = __expf(x0 - mn);
            float p1 = __expf(x1 - mn);
            float p2 = __expf(x2 - mn);
            float p3 = __expf(x3 - mn);
            sc[r][lane]      = p0;
            sc[r][lane + 32] = p1;
            sc[r][lane + 64] = p2;
            sc[r][lane + 96] = p3;
            float ps = (p0 + p1) + (p2 + p3);
#pragma unroll
            for (int off = 16; off; off >>= 1)
                ps += __shfl_xor_sync(0xffffffffu, ps, off);
            l_i[i] = l_i[i] * corr + ps;
            m_i[i] = mn;
            o_i[i] *= corr;
        }
        __syncwarp();

        // --- Phase C: O += P @ V  (lane = d, broadcast float4 P loads)
#pragma unroll 4
        for (int jg = 0; jg < 32; jg++) {
            float v0 = vs[jg * 4 + 0][lane];
            float v1 = vs[jg * 4 + 1][lane];
            float v2 = vs[jg * 4 + 2][lane];
            float v3 = vs[jg * 4 + 3][lane];
#pragma unroll
            for (int i = 0; i < 16; i++) {
                float4 p = *(const float4*)&sc[w * 16 + i][jg * 4];
                o_i[i] += p.x * v0 + p.y * v1 + p.z * v2 + p.w * v3;
            }
        }
    }

    // Epilogue: normalize, write (b, s, c = h*32 + d)
    int b = bh >> 3, h = bh & 7;
#pragma unroll
    for (int i = 0; i < 16; i++) {
        int s = m0 + w * 16 + i;
        g_att[(b * 1024 + s) * 256 + h * 32 + lane] = o_i[i] / l_i[i];
    }
}

// ---------------------------------------------------------------------------
// K6: output projection, computed directly transposed:
// out[b, c, s] = sum_k out_w[c,k] * att[b,s,k] + out_b[c] + x[b,c,s]
// Tile 128(c) x 128(s) x16, 8x8 microtile. grid = (8 s, 2 c, 16 b)
// ---------------------------------------------------------------------------
__global__ void __launch_bounds__(256) k_oproj(const float* __restrict__ w,
                                               const float* __restrict__ bias,
                                               const float* __restrict__ x,
                                               float* __restrict__ out) {
    __shared__ float As[16][132];   // k x c
    __shared__ float Bs[16][132];   // k x s
    int s0 = blockIdx.x * 128;
    int c0 = blockIdx.y * 128;
    int b  = blockIdx.z;
    int tid = threadIdx.x;
    int tr = tid >> 4, tc = tid & 15;
    float acc[8][8];
#pragma unroll
    for (int r = 0; r < 8; r++)
#pragma unroll
        for (int c = 0; c < 8; c++) acc[r][c] = 0.0f;

    for (int k0 = 0; k0 < 256; k0 += 16) {
#pragma unroll
        for (int i = 0; i < 2; i++) {
            int idx = tid + i * 256;
            int row = idx >> 2, kq = idx & 3;
            float4 v = *(const float4*)&w[(c0 + row) * 256 + k0 + kq * 4];
            As[kq * 4 + 0][row] = v.x;
            As[kq * 4 + 1][row] = v.y;
            As[kq * 4 + 2][row] = v.z;
            As[kq * 4 + 3][row] = v.w;
        }
#pragma unroll
        for (int i = 0; i < 2; i++) {
            int idx = tid + i * 256;
            int row = idx >> 2, kq = idx & 3;
            float4 v = *(const float4*)&g_att[(b * 1024 + s0 + row) * 256 + k0 + kq * 4];
            Bs[kq * 4 + 0][row] = v.x;
            Bs[kq * 4 + 1][row] = v.y;
            Bs[kq * 4 + 2][row] = v.z;
            Bs[kq * 4 + 3][row] = v.w;
        }
        __syncthreads();
#pragma unroll
        for (int kk = 0; kk < 16; kk++) {
            float4 a0 = *(const float4*)&As[kk][tr * 4];
            float4 a1 = *(const float4*)&As[kk][tr * 4 + 64];
            float4 b0 = *(const float4*)&Bs[kk][tc * 4];
            float4 b1 = *(const float4*)&Bs[kk][tc * 4 + 64];
            float ar[8] = {a0.x, a0.y, a0.z, a0.w, a1.x, a1.y, a1.z, a1.w};
            float bc[8] = {b0.x, b0.y, b0.z, b0.w, b1.x, b1.y, b1.z, b1.w};
#pragma unroll
            for (int r = 0; r < 8; r++)
#pragma unroll
                for (int c = 0; c < 8; c++) acc[r][c] += ar[r] * bc[c];
        }
        __syncthreads();
    }

    // fused bias + residual, coalesced float4 stores
#pragma unroll
    for (int rr = 0; rr < 2; rr++)
#pragma unroll
    for (int r = 0; r < 4; r++) {
        int cg = c0 + tr * 4 + rr * 64 + r;
        float bv = bias[cg];
#pragma unroll
        for (int cc = 0; cc < 2; cc++) {
            int col = s0 + tc * 4 + cc * 64;
            int idx = (b * 256 + cg) * 1024 + col;
            float4 xr = *(const float4*)&x[idx];
            float4 val;
            val.x = acc[rr * 4 + r][cc * 4 + 0] + bv + xr.x;
            val.y = acc[rr * 4 + r][cc * 4 + 1] + bv + xr.y;
            val.z = acc[rr * 4 + r][cc * 4 + 2] + bv + xr.z;
            val.w = acc[rr * 4 + r][cc * 4 + 3] + bv + xr.w;
            *(float4*)&out[idx] = val;
        }
    }
}

// ---------------------------------------------------------------------------
extern "C" void kernel_launch(void* const* d_in, const int* in_sizes, int n_in,
                              void* d_out, int out_size) {
    const float* x      = (const float*)d_in[0];
    const float* t_emb  = (const float*)d_in[1];
    const float* c_emb  = (const float*)d_in[2];
    const float* gn_w   = (const float*)d_in[3];
    const float* gn_b   = (const float*)d_in[4];
    const float* proj_w = (const float*)d_in[5];
    const float* proj_b = (const float*)d_in[6];
    const float* qkv_w  = (const float*)d_in[7];
    const float* qkv_b  = (const float*)d_in[8];
    const float* out_w  = (const float*)d_in[9];
    const float* out_b  = (const float*)d_in[10];
    float* out = (float*)d_out;

    // Idempotent attribute set (host-side, capture-safe): 117KB dynamic smem.
    cudaFuncSetAttribute(k_attn, cudaFuncAttributeMaxDynamicSharedMemorySize,
                         SMEM_ATTN);

    k_adaln<<<16, 640>>>(t_emb, c_emb, proj_w, proj_b);
    k_gnstat<<<128, 256>>>(x);
    k_gnapply<<<dim3(32, 16), 256>>>(x, gn_w, gn_b);
    k_qkv<<<dim3(6, 128), 256>>>(qkv_w, qkv_b);
    k_attn<<<dim3(128, 8), 256, SMEM_ATTN>>>();
    k_oproj<<<dim3(8, 2, 16), 256>>>(out_w, out_b, x, out);
}

// round 7
// speedup vs baseline: 1.2267x; 1.0682x over previous
#include <cuda_runtime.h>
#include <math.h>

// Problem constants
static const int BB   = 16;
static const int CC   = 256;
static const int SS   = 1024;   // 32*32
static const int NH   = 8;
static const int DKk  = 32;
static const int GR   = 8;
static const int TDIM = 512;
static const int CDIM = 128;
static const int INDIM = 640;   // TDIM + CDIM
static const int TWOC = 512;

typedef unsigned long long u64;

// ---- packed f32x2 helpers (sm_100a FFMA2 path; ptxas never emits these) ----
__device__ __forceinline__ u64 pack2(float lo, float hi) {
    u64 r;
    asm("mov.b64 %0, {%1, %2};"
        : "=l"(r) : "r"(__float_as_uint(lo)), "r"(__float_as_uint(hi)));
    return r;
}
__device__ __forceinline__ u64 dup2(float v) { return pack2(v, v); }
__device__ __forceinline__ float2 unpack2(u64 v) {
    unsigned lo, hi;
    asm("mov.b64 {%0, %1}, %2;" : "=r"(lo), "=r"(hi) : "l"(v));
    return make_float2(__uint_as_float(lo), __uint_as_float(hi));
}
__device__ __forceinline__ void fma2(u64& acc, u64 a, u64 b) {
    asm("fma.rn.f32x2 %0, %1, %2, %3;" : "=l"(acc) : "l"(a), "l"(b), "l"(acc));
}
__device__ __forceinline__ u64 add2(u64 a, u64 b) {
    u64 r; asm("add.rn.f32x2 %0, %1, %2;" : "=l"(r) : "l"(a), "l"(b)); return r;
}
__device__ __forceinline__ u64 mul2(u64 a, u64 b) {
    u64 r; asm("mul.rn.f32x2 %0, %1, %2;" : "=l"(r) : "l"(a), "l"(b)); return r;
}

union F4U { float4 f; u64 u[2]; float s[4]; };

// Device scratch (allocations are forbidden; globals are allowed)
__device__ float g_params[BB * TWOC];       // adaLN gamma/beta, (b, 2C)
__device__ float g_mean[BB * GR];
__device__ float g_rstd[BB * GR];
__device__ float g_xn[BB * SS * CC];        // normalized input, (b, s, c)
__device__ float g_q[BB * NH * SS * DKk];   // (b,h,s,d)
__device__ float g_k[BB * NH * SS * DKk];
__device__ float g_v[BB * NH * SS * DKk];
__device__ float g_att[BB * SS * CC];       // attention output, (b, s, c)

// ---------------------------------------------------------------------------
// K1: adaLN projection. grid = 16, block = 640
// ---------------------------------------------------------------------------
__global__ void k_adaln(const float* __restrict__ t_emb,
                        const float* __restrict__ c_emb,
                        const float* __restrict__ pw,
                        const float* __restrict__ pb) {
    __shared__ float sin_[INDIM];
    int b = blockIdx.x;
    int t = threadIdx.x;            // 0..639
    float v = (t < TDIM) ? t_emb[b * TDIM + t] : c_emb[b * CDIM + (t - TDIM)];
    sin_[t] = v / (1.0f + expf(-v));
    __syncthreads();
    if (t < TWOC) {
        const float* wr = pw + t * INDIM;
        float acc = pb[t];
#pragma unroll 8
        for (int i = 0; i < INDIM; i++) acc += sin_[i] * wr[i];
        g_params[b * TWOC + t] = acc;
    }
}

// ---------------------------------------------------------------------------
// K2: GroupNorm statistics. grid = 128, block = 256
// ---------------------------------------------------------------------------
__global__ void k_gnstat(const float* __restrict__ x) {
    int bg = blockIdx.x;
    const float4* p = (const float4*)(x + (size_t)bg * 32768);
    float s = 0.0f, ss = 0.0f;
    for (int i = threadIdx.x; i < 8192; i += 256) {
        float4 v = p[i];
        s  += v.x + v.y + v.z + v.w;
        ss += v.x * v.x + v.y * v.y + v.z * v.z + v.w * v.w;
    }
#pragma unroll
    for (int o = 16; o; o >>= 1) {
        s  += __shfl_xor_sync(0xffffffffu, s, o);
        ss += __shfl_xor_sync(0xffffffffu, ss, o);
    }
    __shared__ float rs[8], rss[8];
    int w = threadIdx.x >> 5, l = threadIdx.x & 31;
    if (l == 0) { rs[w] = s; rss[w] = ss; }
    __syncthreads();
    if (threadIdx.x == 0) {
        float S = 0.0f, SSum = 0.0f;
#pragma unroll
        for (int i = 0; i < 8; i++) { S += rs[i]; SSum += rss[i]; }
        float m = S / 32768.0f;
        float var = SSum / 32768.0f - m * m;
        g_mean[bg] = m;
        g_rstd[bg] = rsqrtf(var + 1e-6f);
    }
}

// ---------------------------------------------------------------------------
// K3: apply GN + adaLN affine, transpose (b,c,s) -> (b,s,c).
// grid = (32 s-tiles, 16 b), block = 256.
// ---------------------------------------------------------------------------
__global__ void k_gnapply(const float* __restrict__ x,
                          const float* __restrict__ gw,
                          const float* __restrict__ gb) {
    __shared__ float tile[CC][33];
    int b = blockIdx.y;
    int s0 = blockIdx.x * 32;
    int t = threadIdx.x;
    int w = t >> 5, sl = t & 31;
#pragma unroll
    for (int k = 0; k < 32; k++) {
        int c = k * 8 + w;
        float v = x[(b * CC + c) * SS + s0 + sl];
        int g = c >> 5;
        float vn = (v - g_mean[b * GR + g]) * g_rstd[b * GR + g];
        vn = vn * gw[c] + gb[c];
        float gam = g_params[b * TWOC + c];
        float bet = g_params[b * TWOC + CC + c];
        tile[c][sl] = vn * (1.0f + gam) + bet;
    }
    __syncthreads();
#pragma unroll
    for (int k = 0; k < 32; k++) {
        g_xn[(b * SS + s0 + k) * CC + t] = tile[t][k];
    }
}

// ---------------------------------------------------------------------------
// K4: QKV GEMM, f32x2 microkernel. Tile 128x128x16, 8x8 (as 8x4 pairs).
// grid = (6, 128)
// ---------------------------------------------------------------------------
__global__ void __launch_bounds__(256) k_qkv(const float* __restrict__ w,
                                             const float* __restrict__ bias) {
    __shared__ float As[16][132];
    __shared__ float Bs[16][132];
    int m0 = blockIdx.y * 128;
    int o0 = blockIdx.x * 128;
    int tid = threadIdx.x;
    int tr = tid >> 4, tc = tid & 15;
    u64 acc[8][4];
#pragma unroll
    for (int r = 0; r < 8; r++)
#pragma unroll
        for (int c = 0; c < 4; c++) acc[r][c] = 0ULL;

    for (int k0 = 0; k0 < 256; k0 += 16) {
#pragma unroll
        for (int i = 0; i < 2; i++) {
            int idx = tid + i * 256;          // 0..511
            int row = idx >> 2, kq = idx & 3;
            float4 v = *(const float4*)&g_xn[(m0 + row) * 256 + k0 + kq * 4];
            As[kq * 4 + 0][row] = v.x;
            As[kq * 4 + 1][row] = v.y;
            As[kq * 4 + 2][row] = v.z;
            As[kq * 4 + 3][row] = v.w;
        }
#pragma unroll
        for (int i = 0; i < 2; i++) {
            int idx = tid + i * 256;
            int row = idx >> 2, kq = idx & 3;
            float4 v = *(const float4*)&w[(o0 + row) * 256 + k0 + kq * 4];
            Bs[kq * 4 + 0][row] = v.x;
            Bs[kq * 4 + 1][row] = v.y;
            Bs[kq * 4 + 2][row] = v.z;
            Bs[kq * 4 + 3][row] = v.w;
        }
        __syncthreads();
#pragma unroll
        for (int kk = 0; kk < 16; kk++) {
            F4U a0, a1, b0, b1;
            a0.f = *(const float4*)&As[kk][tr * 4];
            a1.f = *(const float4*)&As[kk][tr * 4 + 64];
            b0.f = *(const float4*)&Bs[kk][tc * 4];
            b1.f = *(const float4*)&Bs[kk][tc * 4 + 64];
            u64 bu[4] = {b0.u[0], b0.u[1], b1.u[0], b1.u[1]};
            float ar[8] = {a0.s[0], a0.s[1], a0.s[2], a0.s[3],
                           a1.s[0], a1.s[1], a1.s[2], a1.s[3]};
#pragma unroll
            for (int r = 0; r < 8; r++) {
                u64 ad = dup2(ar[r]);
#pragma unroll
                for (int c = 0; c < 4; c++) fma2(acc[r][c], ad, bu[c]);
            }
        }
        __syncthreads();
    }

    float* dst; int obase;
    if (o0 < 256)      { dst = g_q; obase = o0; }
    else if (o0 < 512) { dst = g_k; obase = o0 - 256; }
    else               { dst = g_v; obase = o0 - 512; }
    int b = m0 >> 10;
    F4U bias0, bias1;
    bias0.f = *(const float4*)&bias[o0 + tc * 4];
    bias1.f = *(const float4*)&bias[o0 + tc * 4 + 64];
#pragma unroll
    for (int rr = 0; rr < 2; rr++)
#pragma unroll
    for (int r = 0; r < 4; r++) {
        int s = (m0 + tr * 4 + rr * 64 + r) & 1023;
#pragma unroll
        for (int cc = 0; cc < 2; cc++) {
            int col = obase + tc * 4 + cc * 64;
            int h = col >> 5, d = col & 31;
            F4U val;
            val.u[0] = add2(acc[rr * 4 + r][cc * 2 + 0], cc ? bias1.u[0] : bias0.u[0]);
            val.u[1] = add2(acc[rr * 4 + r][cc * 2 + 1], cc ? bias1.u[1] : bias0.u[1]);
            *(float4*)&dst[((b * 8 + h) * 1024 + s) * 32 + d] = val.f;
        }
    }
}

// ---------------------------------------------------------------------------
// K5: flash attention, 128q x 128k tiles, f32x2 in both matmul phases.
// grid = (128 bh, 8 q-tiles), 256 thr, 117KB dynamic smem.
// ---------------------------------------------------------------------------
static const int SMEM_ATTN = 29952 * 4;  // 119808 bytes

__global__ void __launch_bounds__(256, 1) k_attn() {
    extern __shared__ float sm[];
    float (*qT)[132] = (float(*)[132])(sm);           // 32 x 132 (d-major Q^T)
    float (*kT)[132] = (float(*)[132])(sm + 4224);    // 32 x 132 (d-major K^T)
    float (*vs)[36]  = (float(*)[36]) (sm + 8448);    // 128 x 36
    float (*sc)[132] = (float(*)[132])(sm + 13056);   // 128 x 132 scores/probs

    int bh = blockIdx.x;
    int m0 = blockIdx.y * 128;
    int tid = threadIdx.x;
    int w = tid >> 5, lane = tid & 31;
    int tr = tid >> 4, tc = tid & 15;
    const float scale = 0.17677669529663687f;   // 1/sqrt(32)
    int base = bh * (1024 * 32);

    // Load Q tile transposed, pre-scaled
#pragma unroll
    for (int i = 0; i < 4; i++) {
        int idx = tid + i * 256;         // 0..1023
        int row = idx >> 3, dq = idx & 7;
        float4 v = *(const float4*)&g_q[base + (m0 + row) * 32 + dq * 4];
        qT[dq * 4 + 0][row] = v.x * scale;
        qT[dq * 4 + 1][row] = v.y * scale;
        qT[dq * 4 + 2][row] = v.z * scale;
        qT[dq * 4 + 3][row] = v.w * scale;
    }

    float m_i[16], l_i[16];
    u64 o2[16];   // (even-j partial, odd-j partial)
#pragma unroll
    for (int i = 0; i < 16; i++) { m_i[i] = -1e30f; l_i[i] = 0.0f; o2[i] = 0ULL; }

    for (int j0 = 0; j0 < 1024; j0 += 128) {
        __syncthreads();   // previous tile fully consumed
#pragma unroll
        for (int i = 0; i < 4; i++) {
            int idx = tid + i * 256;
            int row = idx >> 3, dq = idx & 7;
            float4 kv = *(const float4*)&g_k[base + (j0 + row) * 32 + dq * 4];
            kT[dq * 4 + 0][row] = kv.x;
            kT[dq * 4 + 1][row] = kv.y;
            kT[dq * 4 + 2][row] = kv.z;
            kT[dq * 4 + 3][row] = kv.w;
            float4 vv = *(const float4*)&g_v[base + (j0 + row) * 32 + dq * 4];
            *(float4*)&vs[row][dq * 4] = vv;
        }
        __syncthreads();

        // --- Phase A: scores 128x128, 8x8 microtile as 8x4 f32x2 pairs
        {
            u64 acc[8][4];
#pragma unroll
            for (int r = 0; r < 8; r++)
#pragma unroll
                for (int c = 0; c < 4; c++) acc[r][c] = 0ULL;
#pragma unroll
            for (int d = 0; d < 32; d++) {
                F4U a0, a1, b0, b1;
                a0.f = *(const float4*)&qT[d][tr * 4];
                a1.f = *(const float4*)&qT[d][tr * 4 + 64];
                b0.f = *(const float4*)&kT[d][tc * 4];
                b1.f = *(const float4*)&kT[d][tc * 4 + 64];
                u64 bu[4] = {b0.u[0], b0.u[1], b1.u[0], b1.u[1]};
                float ar[8] = {a0.s[0], a0.s[1], a0.s[2], a0.s[3],
                               a1.s[0], a1.s[1], a1.s[2], a1.s[3]};
#pragma unroll
                for (int r = 0; r < 8; r++) {
                    u64 ad = dup2(ar[r]);
#pragma unroll
                    for (int c = 0; c < 4; c++) fma2(acc[r][c], ad, bu[c]);
                }
            }
#pragma unroll
            for (int rr = 0; rr < 2; rr++)
#pragma unroll
            for (int r = 0; r < 4; r++) {
                int qrow = tr * 4 + rr * 64 + r;
#pragma unroll
                for (int cc = 0; cc < 2; cc++) {
                    F4U val;
                    val.u[0] = acc[rr * 4 + r][cc * 2 + 0];
                    val.u[1] = acc[rr * 4 + r][cc * 2 + 1];
                    *(float4*)&sc[qrow][tc * 4 + cc * 64] = val.f;
                }
            }
        }
        __syncthreads();

        // --- Phase B: online softmax, warp w owns rows w*16..w*16+15
#pragma unroll
        for (int i = 0; i < 16; i++) {
            int r = w * 16 + i;
            float x0 = sc[r][lane];
            float x1 = sc[r][lane + 32];
            float x2 = sc[r][lane + 64];
            float x3 = sc[r][lane + 96];
            float t = fmaxf(fmaxf(x0, x1), fmaxf(x2, x3));
#pragma unroll
            for (int off = 16; off; off >>= 1)
                t = fmaxf(t, __shfl_xor_sync(0xffffffffu, t, off));
            float mn = fmaxf(m_i[i], t);
            float corr = __expf(m_i[i] - mn);
            float p0 = __expf(x0 - mn);
            float p1 = __expf(x1 - mn);
            float p2 = __expf(x2 - mn);
            float p3 = __expf(x3 - mn);
            sc[r][lane]      = p0;
            sc[r][lane + 32] = p1;
            sc[r][lane + 64] = p2;
            sc[r][lane + 96] = p3;
            float ps = (p0 + p1) + (p2 + p3);
#pragma unroll
            for (int off = 16; off; off >>= 1)
                ps += __shfl_xor_sync(0xffffffffu, ps, off);
            l_i[i] = l_i[i] * corr + ps;
            m_i[i] = mn;
            o2[i] = mul2(o2[i], dup2(corr));
        }
        __syncwarp();

        // --- Phase C: O += P @ V, paired over adjacent j (p float4 = 2 pairs)
#pragma unroll 4
        for (int jg = 0; jg < 32; jg++) {
            u64 v01 = pack2(vs[jg * 4 + 0][lane], vs[jg * 4 + 1][lane]);
            u64 v23 = pack2(vs[jg * 4 + 2][lane], vs[jg * 4 + 3][lane]);
#pragma unroll
            for (int i = 0; i < 16; i++) {
                F4U p;
                p.f = *(const float4*)&sc[w * 16 + i][jg * 4];
                fma2(o2[i], p.u[0], v01);
                fma2(o2[i], p.u[1], v23);
            }
        }
    }

    // Epilogue: collapse pair halves, normalize, write (b, s, c = h*32 + d)
    int b = bh >> 3, h = bh & 7;
#pragma unroll
    for (int i = 0; i < 16; i++) {
        int s = m0 + w * 16 + i;
        float2 hv = unpack2(o2[i]);
        g_att[(b * 1024 + s) * 256 + h * 32 + lane] = (hv.x + hv.y) / l_i[i];
    }
}

// ---------------------------------------------------------------------------
// K6: output projection (transposed) + bias + residual, f32x2 microkernel.
// grid = (8 s, 2 c, 16 b)
// ---------------------------------------------------------------------------
__global__ void __launch_bounds__(256) k_oproj(const float* __restrict__ w,
                                               const float* __restrict__ bias,
                                               const float* __restrict__ x,
                                               float* __restrict__ out) {
    __shared__ float As[16][132];   // k x c
    __shared__ float Bs[16][132];   // k x s
    int s0 = blockIdx.x * 128;
    int c0 = blockIdx.y * 128;
    int b  = blockIdx.z;
    int tid = threadIdx.x;
    int tr = tid >> 4, tc = tid & 15;
    u64 acc[8][4];
#pragma unroll
    for (int r = 0; r < 8; r++)
#pragma unroll
        for (int c = 0; c < 4; c++) acc[r][c] = 0ULL;

    for (int k0 = 0; k0 < 256; k0 += 16) {
#pragma unroll
        for (int i = 0; i < 2; i++) {
            int idx = tid + i * 256;
            int row = idx >> 2, kq = idx & 3;
            float4 v = *(const float4*)&w[(c0 + row) * 256 + k0 + kq * 4];
            As[kq * 4 + 0][row] = v.x;
            As[kq * 4 + 1][row] = v.y;
            As[kq * 4 + 2][row] = v.z;
            As[kq * 4 + 3][row] = v.w;
        }
#pragma unroll
        for (int i = 0; i < 2; i++) {
            int idx = tid + i * 256;
            int row = idx >> 2, kq = idx & 3;
            float4 v = *(const float4*)&g_att[(b * 1024 + s0 + row) * 256 + k0 + kq * 4];
            Bs[kq * 4 + 0][row] = v.x;
            Bs[kq * 4 + 1][row] = v.y;
            Bs[kq * 4 + 2][row] = v.z;
            Bs[kq * 4 + 3][row] = v.w;
        }
        __syncthreads();
#pragma unroll
        for (int kk = 0; kk < 16; kk++) {
            F4U a0, a1, b0, b1;
            a0.f = *(const float4*)&As[kk][tr * 4];
            a1.f = *(const float4*)&As[kk][tr * 4 + 64];
            b0.f = *(const float4*)&Bs[kk][tc * 4];
            b1.f = *(const float4*)&Bs[kk][tc * 4 + 64];
            u64 bu[4] = {b0.u[0], b0.u[1], b1.u[0], b1.u[1]};
            float ar[8] = {a0.s[0], a0.s[1], a0.s[2], a0.s[3],
                           a1.s[0], a1.s[1], a1.s[2], a1.s[3]};
#pragma unroll
            for (int r = 0; r < 8; r++) {
                u64 ad = dup2(ar[r]);
#pragma unroll
                for (int c = 0; c < 4; c++) fma2(acc[r][c], ad, bu[c]);
            }
        }
        __syncthreads();
    }

    // fused bias + residual, coalesced float4 stores
#pragma unroll
    for (int rr = 0; rr < 2; rr++)
#pragma unroll
    for (int r = 0; r < 4; r++) {
        int cg = c0 + tr * 4 + rr * 64 + r;
        u64 bv = dup2(bias[cg]);
#pragma unroll
        for (int cc = 0; cc < 2; cc++) {
            int col = s0 + tc * 4 + cc * 64;
            int idx = (b * 256 + cg) * 1024 + col;
            F4U xr; xr.f = *(const float4*)&x[idx];
            F4U val;
            val.u[0] = add2(add2(acc[rr * 4 + r][cc * 2 + 0], bv), xr.u[0]);
            val.u[1] = add2(add2(acc[rr * 4 + r][cc * 2 + 1], bv), xr.u[1]);
            *(float4*)&out[idx] = val.f;
        }
    }
}

// ---------------------------------------------------------------------------
extern "C" void kernel_launch(void* const* d_in, const int* in_sizes, int n_in,
                              void* d_out, int out_size) {
    const float* x      = (const float*)d_in[0];
    const float* t_emb  = (const float*)d_in[1];
    const float* c_emb  = (const float*)d_in[2];
    const float* gn_w   = (const float*)d_in[3];
    const float* gn_b   = (const float*)d_in[4];
    const float* proj_w = (const float*)d_in[5];
    const float* proj_b = (const float*)d_in[6];
    const float* qkv_w  = (const float*)d_in[7];
    const float* qkv_b  = (const float*)d_in[8];
    const float* out_w  = (const float*)d_in[9];
    const float* out_b  = (const float*)d_in[10];
    float* out = (float*)d_out;

    // Idempotent attribute set (host-side, capture-safe): 117KB dynamic smem.
    cudaFuncSetAttribute(k_attn, cudaFuncAttributeMaxDynamicSharedMemorySize,
                         SMEM_ATTN);

    k_adaln<<<16, 640>>>(t_emb, c_emb, proj_w, proj_b);
    k_gnstat<<<128, 256>>>(x);
    k_gnapply<<<dim3(32, 16), 256>>>(x, gn_w, gn_b);
    k_qkv<<<dim3(6, 128), 256>>>(qkv_w, qkv_b);
    k_attn<<<dim3(128, 8), 256, SMEM_ATTN>>>();
    k_oproj<<<dim3(8, 2, 16), 256>>>(out_w, out_b, x, out);
}

// round 8
// speedup vs baseline: 1.9164x; 1.5623x over previous
#include <cuda_runtime.h>
#include <math.h>

// Problem constants
static const int BB   = 16;
static const int CC   = 256;
static const int SS   = 1024;   // 32*32
static const int NH   = 8;
static const int DKk  = 32;
static const int GR   = 8;
static const int TDIM = 512;
static const int CDIM = 128;
static const int INDIM = 640;   // TDIM + CDIM
static const int TWOC = 512;

typedef unsigned long long u64;

// ---- packed f32x2 helpers (FFMA2 path for the projections) ----
__device__ __forceinline__ u64 pack2(float lo, float hi) {
    u64 r;
    asm("mov.b64 %0, {%1, %2};"
        : "=l"(r) : "r"(__float_as_uint(lo)), "r"(__float_as_uint(hi)));
    return r;
}
__device__ __forceinline__ u64 dup2(float v) { return pack2(v, v); }
__device__ __forceinline__ void fma2(u64& acc, u64 a, u64 b) {
    asm("fma.rn.f32x2 %0, %1, %2, %3;" : "=l"(acc) : "l"(a), "l"(b), "l"(acc));
}
__device__ __forceinline__ u64 add2(u64 a, u64 b) {
    u64 r; asm("add.rn.f32x2 %0, %1, %2;" : "=l"(r) : "l"(a), "l"(b)); return r;
}

// ---- tf32 helpers ----
__device__ __forceinline__ unsigned to_tf32(float f) {
    unsigned r; asm("cvt.rna.tf32.f32 %0, %1;" : "=r"(r) : "f"(f)); return r;
}
__device__ __forceinline__ void mma_tf32(float& d0, float& d1, float& d2, float& d3,
                                         unsigned a0, unsigned a1, unsigned a2, unsigned a3,
                                         unsigned b0, unsigned b1) {
    asm("mma.sync.aligned.m16n8k8.row.col.f32.tf32.tf32.f32 "
        "{%0,%1,%2,%3}, {%4,%5,%6,%7}, {%8,%9}, {%0,%1,%2,%3};"
        : "+f"(d0), "+f"(d1), "+f"(d2), "+f"(d3)
        : "r"(a0), "r"(a1), "r"(a2), "r"(a3), "r"(b0), "r"(b1));
}

union F4U { float4 f; u64 u[2]; float s[4]; };

// Device scratch
__device__ float g_params[BB * TWOC];
__device__ float g_mean[BB * GR];
__device__ float g_rstd[BB * GR];
__device__ float g_xn[BB * SS * CC];
__device__ float g_q[BB * NH * SS * DKk];   // (b,h,s,d)
__device__ float g_k[BB * NH * SS * DKk];
__device__ float g_v[BB * NH * SS * DKk];
__device__ float g_att[BB * SS * CC];       // (b, s, c)

// ---------------------------------------------------------------------------
// K1: adaLN projection. grid = 16, block = 640
// ---------------------------------------------------------------------------
__global__ void k_adaln(const float* __restrict__ t_emb,
                        const float* __restrict__ c_emb,
                        const float* __restrict__ pw,
                        const float* __restrict__ pb) {
    __shared__ float sin_[INDIM];
    int b = blockIdx.x;
    int t = threadIdx.x;
    float v = (t < TDIM) ? t_emb[b * TDIM + t] : c_emb[b * CDIM + (t - TDIM)];
    sin_[t] = v / (1.0f + expf(-v));
    __syncthreads();
    if (t < TWOC) {
        const float* wr = pw + t * INDIM;
        float acc = pb[t];
#pragma unroll 8
        for (int i = 0; i < INDIM; i++) acc += sin_[i] * wr[i];
        g_params[b * TWOC + t] = acc;
    }
}

// ---------------------------------------------------------------------------
// K2: GroupNorm statistics. grid = 128, block = 256
// ---------------------------------------------------------------------------
__global__ void k_gnstat(const float* __restrict__ x) {
    int bg = blockIdx.x;
    const float4* p = (const float4*)(x + (size_t)bg * 32768);
    float s = 0.0f, ss = 0.0f;
    for (int i = threadIdx.x; i < 8192; i += 256) {
        float4 v = p[i];
        s  += v.x + v.y + v.z + v.w;
        ss += v.x * v.x + v.y * v.y + v.z * v.z + v.w * v.w;
    }
#pragma unroll
    for (int o = 16; o; o >>= 1) {
        s  += __shfl_xor_sync(0xffffffffu, s, o);
        ss += __shfl_xor_sync(0xffffffffu, ss, o);
    }
    __shared__ float rs[8], rss[8];
    int w = threadIdx.x >> 5, l = threadIdx.x & 31;
    if (l == 0) { rs[w] = s; rss[w] = ss; }
    __syncthreads();
    if (threadIdx.x == 0) {
        float S = 0.0f, SSum = 0.0f;
#pragma unroll
        for (int i = 0; i < 8; i++) { S += rs[i]; SSum += rss[i]; }
        float m = S / 32768.0f;
        float var = SSum / 32768.0f - m * m;
        g_mean[bg] = m;
        g_rstd[bg] = rsqrtf(var + 1e-6f);
    }
}

// ---------------------------------------------------------------------------
// K3: apply GN + adaLN affine, transpose (b,c,s) -> (b,s,c).
// ---------------------------------------------------------------------------
__global__ void k_gnapply(const float* __restrict__ x,
                          const float* __restrict__ gw,
                          const float* __restrict__ gb) {
    __shared__ float tile[CC][33];
    int b = blockIdx.y;
    int s0 = blockIdx.x * 32;
    int t = threadIdx.x;
    int w = t >> 5, sl = t & 31;
#pragma unroll
    for (int k = 0; k < 32; k++) {
        int c = k * 8 + w;
        float v = x[(b * CC + c) * SS + s0 + sl];
        int g = c >> 5;
        float vn = (v - g_mean[b * GR + g]) * g_rstd[b * GR + g];
        vn = vn * gw[c] + gb[c];
        float gam = g_params[b * TWOC + c];
        float bet = g_params[b * TWOC + CC + c];
        tile[c][sl] = vn * (1.0f + gam) + bet;
    }
    __syncthreads();
#pragma unroll
    for (int k = 0; k < 32; k++) {
        g_xn[(b * SS + s0 + k) * CC + t] = tile[t][k];
    }
}

// ---------------------------------------------------------------------------
// K4: QKV GEMM, f32x2 microkernel (unchanged from R6). grid = (6, 128)
// ---------------------------------------------------------------------------
__global__ void __launch_bounds__(256) k_qkv(const float* __restrict__ w,
                                             const float* __restrict__ bias) {
    __shared__ float As[16][132];
    __shared__ float Bs[16][132];
    int m0 = blockIdx.y * 128;
    int o0 = blockIdx.x * 128;
    int tid = threadIdx.x;
    int tr = tid >> 4, tc = tid & 15;
    u64 acc[8][4];
#pragma unroll
    for (int r = 0; r < 8; r++)
#pragma unroll
        for (int c = 0; c < 4; c++) acc[r][c] = 0ULL;

    for (int k0 = 0; k0 < 256; k0 += 16) {
#pragma unroll
        for (int i = 0; i < 2; i++) {
            int idx = tid + i * 256;
            int row = idx >> 2, kq = idx & 3;
            float4 v = *(const float4*)&g_xn[(m0 + row) * 256 + k0 + kq * 4];
            As[kq * 4 + 0][row] = v.x;
            As[kq * 4 + 1][row] = v.y;
            As[kq * 4 + 2][row] = v.z;
            As[kq * 4 + 3][row] = v.w;
        }
#pragma unroll
        for (int i = 0; i < 2; i++) {
            int idx = tid + i * 256;
            int row = idx >> 2, kq = idx & 3;
            float4 v = *(const float4*)&w[(o0 + row) * 256 + k0 + kq * 4];
            Bs[kq * 4 + 0][row] = v.x;
            Bs[kq * 4 + 1][row] = v.y;
            Bs[kq * 4 + 2][row] = v.z;
            Bs[kq * 4 + 3][row] = v.w;
        }
        __syncthreads();
#pragma unroll
        for (int kk = 0; kk < 16; kk++) {
            F4U a0, a1, b0, b1;
            a0.f = *(const float4*)&As[kk][tr * 4];
            a1.f = *(const float4*)&As[kk][tr * 4 + 64];
            b0.f = *(const float4*)&Bs[kk][tc * 4];
            b1.f = *(const float4*)&Bs[kk][tc * 4 + 64];
            u64 bu[4] = {b0.u[0], b0.u[1], b1.u[0], b1.u[1]};
            float ar[8] = {a0.s[0], a0.s[1], a0.s[2], a0.s[3],
                           a1.s[0], a1.s[1], a1.s[2], a1.s[3]};
#pragma unroll
            for (int r = 0; r < 8; r++) {
                u64 ad = dup2(ar[r]);
#pragma unroll
                for (int c = 0; c < 4; c++) fma2(acc[r][c], ad, bu[c]);
            }
        }
        __syncthreads();
    }

    float* dst; int obase;
    if (o0 < 256)      { dst = g_q; obase = o0; }
    else if (o0 < 512) { dst = g_k; obase = o0 - 256; }
    else               { dst = g_v; obase = o0 - 512; }
    int b = m0 >> 10;
    F4U bias0, bias1;
    bias0.f = *(const float4*)&bias[o0 + tc * 4];
    bias1.f = *(const float4*)&bias[o0 + tc * 4 + 64];
#pragma unroll
    for (int rr = 0; rr < 2; rr++)
#pragma unroll
    for (int r = 0; r < 4; r++) {
        int s = (m0 + tr * 4 + rr * 64 + r) & 1023;
#pragma unroll
        for (int cc = 0; cc < 2; cc++) {
            int col = obase + tc * 4 + cc * 64;
            int h = col >> 5, d = col & 31;
            F4U val;
            val.u[0] = add2(acc[rr * 4 + r][cc * 2 + 0], cc ? bias1.u[0] : bias0.u[0]);
            val.u[1] = add2(acc[rr * 4 + r][cc * 2 + 1], cc ? bias1.u[1] : bias0.u[1]);
            *(float4*)&dst[((b * 8 + h) * 1024 + s) * 32 + d] = val.f;
        }
    }
}

// ---------------------------------------------------------------------------
// K5: flash attention on tf32 tensor cores (mma.sync m16n8k8).
// Block: 128 q-rows, 8 warps, warp = 16 q-rows. 8 key tiles of 128.
// grid = (128 bh, 8 q-tiles), 256 thr.
// smem: qT 128x36, kT 128x36, vT 128x40 (tf32), P 128x132 (tf32).
// ---------------------------------------------------------------------------
static const int Q_OFF = 0;                 // 128*36
static const int K_OFF = 128 * 36;          // 4608
static const int V_OFF = K_OFF + 128 * 36;  // 9216
static const int P_OFF = V_OFF + 128 * 40;  // 14336
static const int SMEM_ATTN = (P_OFF + 128 * 132) * 4;  // 124928 bytes

__global__ void __launch_bounds__(256, 1) k_attn() {
    extern __shared__ unsigned smu[];
    unsigned (*qs)[36]  = (unsigned(*)[36])(smu + Q_OFF);
    unsigned (*ks)[36]  = (unsigned(*)[36])(smu + K_OFF);
    unsigned (*vs)[40]  = (unsigned(*)[40])(smu + V_OFF);
    unsigned (*ps)[132] = (unsigned(*)[132])(smu + P_OFF);

    int bh = blockIdx.x;
    int m0 = blockIdx.y * 128;
    int tid = threadIdx.x;
    int w = tid >> 5, lane = tid & 31;
    int gid = lane >> 2, tig = lane & 3;
    const float scale = 0.17677669529663687f;   // 1/sqrt(32)
    int base = bh * (1024 * 32);
    int r0 = 16 * w + gid;        // warp-local absolute q-row (first)
    int r1 = r0 + 8;

    // Load Q tile (scaled) as tf32
#pragma unroll
    for (int i = 0; i < 4; i++) {
        int idx = tid + i * 256;
        int row = idx >> 3, dq = idx & 7;
        float4 v = *(const float4*)&g_q[base + (m0 + row) * 32 + dq * 4];
        qs[row][dq * 4 + 0] = to_tf32(v.x * scale);
        qs[row][dq * 4 + 1] = to_tf32(v.y * scale);
        qs[row][dq * 4 + 2] = to_tf32(v.z * scale);
        qs[row][dq * 4 + 3] = to_tf32(v.w * scale);
    }
    __syncthreads();

    // Cache Q fragments in registers: 4 k-steps x 4 regs
    unsigned qa[4][4];
#pragma unroll
    for (int dk = 0; dk < 4; dk++) {
        qa[dk][0] = qs[r0][8 * dk + tig];
        qa[dk][1] = qs[r1][8 * dk + tig];
        qa[dk][2] = qs[r0][8 * dk + tig + 4];
        qa[dk][3] = qs[r1][8 * dk + tig + 4];
    }

    float m_0 = -1e30f, m_1 = -1e30f, l_0 = 0.0f, l_1 = 0.0f;
    float oacc[4][4];
#pragma unroll
    for (int dn = 0; dn < 4; dn++)
#pragma unroll
        for (int i = 0; i < 4; i++) oacc[dn][i] = 0.0f;

    for (int j0 = 0; j0 < 1024; j0 += 128) {
        __syncthreads();   // previous tile's K/V fully consumed
#pragma unroll
        for (int i = 0; i < 4; i++) {
            int idx = tid + i * 256;
            int row = idx >> 3, dq = idx & 7;
            float4 kv = *(const float4*)&g_k[base + (j0 + row) * 32 + dq * 4];
            ks[row][dq * 4 + 0] = to_tf32(kv.x);
            ks[row][dq * 4 + 1] = to_tf32(kv.y);
            ks[row][dq * 4 + 2] = to_tf32(kv.z);
            ks[row][dq * 4 + 3] = to_tf32(kv.w);
            float4 vv = *(const float4*)&g_v[base + (j0 + row) * 32 + dq * 4];
            vs[row][dq * 4 + 0] = to_tf32(vv.x);
            vs[row][dq * 4 + 1] = to_tf32(vv.y);
            vs[row][dq * 4 + 2] = to_tf32(vv.z);
            vs[row][dq * 4 + 3] = to_tf32(vv.w);
        }
        __syncthreads();

        // --- Phase A: S = Q K^T, warp computes 16 x 128 fragments
        float accS[16][4];
#pragma unroll
        for (int jn = 0; jn < 16; jn++) {
            accS[jn][0] = accS[jn][1] = accS[jn][2] = accS[jn][3] = 0.0f;
#pragma unroll
            for (int dk = 0; dk < 4; dk++) {
                unsigned b0 = ks[jn * 8 + gid][8 * dk + tig];
                unsigned b1 = ks[jn * 8 + gid][8 * dk + tig + 4];
                mma_tf32(accS[jn][0], accS[jn][1], accS[jn][2], accS[jn][3],
                         qa[dk][0], qa[dk][1], qa[dk][2], qa[dk][3], b0, b1);
            }
        }

        // --- Phase B: online softmax in fragment domain
        float mx0 = -1e30f, mx1 = -1e30f;
#pragma unroll
        for (int jn = 0; jn < 16; jn++) {
            mx0 = fmaxf(mx0, fmaxf(accS[jn][0], accS[jn][1]));
            mx1 = fmaxf(mx1, fmaxf(accS[jn][2], accS[jn][3]));
        }
        mx0 = fmaxf(mx0, __shfl_xor_sync(0xffffffffu, mx0, 1));
        mx0 = fmaxf(mx0, __shfl_xor_sync(0xffffffffu, mx0, 2));
        mx1 = fmaxf(mx1, __shfl_xor_sync(0xffffffffu, mx1, 1));
        mx1 = fmaxf(mx1, __shfl_xor_sync(0xffffffffu, mx1, 2));
        float mn0 = fmaxf(m_0, mx0), mn1 = fmaxf(m_1, mx1);
        float corr0 = __expf(m_0 - mn0), corr1 = __expf(m_1 - mn1);
        float sum0 = 0.0f, sum1 = 0.0f;
#pragma unroll
        for (int jn = 0; jn < 16; jn++) {
            float p00 = __expf(accS[jn][0] - mn0);
            float p01 = __expf(accS[jn][1] - mn0);
            float p10 = __expf(accS[jn][2] - mn1);
            float p11 = __expf(accS[jn][3] - mn1);
            sum0 += p00 + p01;
            sum1 += p10 + p11;
            ps[r0][jn * 8 + 2 * tig]     = to_tf32(p00);
            ps[r0][jn * 8 + 2 * tig + 1] = to_tf32(p01);
            ps[r1][jn * 8 + 2 * tig]     = to_tf32(p10);
            ps[r1][jn * 8 + 2 * tig + 1] = to_tf32(p11);
        }
        sum0 += __shfl_xor_sync(0xffffffffu, sum0, 1);
        sum0 += __shfl_xor_sync(0xffffffffu, sum0, 2);
        sum1 += __shfl_xor_sync(0xffffffffu, sum1, 1);
        sum1 += __shfl_xor_sync(0xffffffffu, sum1, 2);
        l_0 = l_0 * corr0 + sum0;
        l_1 = l_1 * corr1 + sum1;
        m_0 = mn0; m_1 = mn1;
#pragma unroll
        for (int dn = 0; dn < 4; dn++) {
            oacc[dn][0] *= corr0; oacc[dn][1] *= corr0;
            oacc[dn][2] *= corr1; oacc[dn][3] *= corr1;
        }
        __syncwarp();   // ps rows are warp-private; order writes before reads

        // --- Phase C: O += P V, 16 k-steps x 4 d-tiles
#pragma unroll
        for (int jk = 0; jk < 16; jk++) {
            unsigned pa0 = ps[r0][8 * jk + tig];
            unsigned pa1 = ps[r1][8 * jk + tig];
            unsigned pa2 = ps[r0][8 * jk + tig + 4];
            unsigned pa3 = ps[r1][8 * jk + tig + 4];
#pragma unroll
            for (int dn = 0; dn < 4; dn++) {
                unsigned b0 = vs[8 * jk + tig][8 * dn + gid];
                unsigned b1 = vs[8 * jk + tig + 4][8 * dn + gid];
                mma_tf32(oacc[dn][0], oacc[dn][1], oacc[dn][2], oacc[dn][3],
                         pa0, pa1, pa2, pa3, b0, b1);
            }
        }
        __syncwarp();   // done with ps before next iteration rewrites
    }

    // Epilogue: normalize, write (b, s, c = h*32 + d)
    int b = bh >> 3, h = bh & 7;
    float inv0 = 1.0f / l_0, inv1 = 1.0f / l_1;
    int s0g = (b * 1024 + m0 + r0) * 256 + h * 32;
    int s1g = (b * 1024 + m0 + r1) * 256 + h * 32;
#pragma unroll
    for (int dn = 0; dn < 4; dn++) {
        int d = dn * 8 + 2 * tig;
        g_att[s0g + d]     = oacc[dn][0] * inv0;
        g_att[s0g + d + 1] = oacc[dn][1] * inv0;
        g_att[s1g + d]     = oacc[dn][2] * inv1;
        g_att[s1g + d + 1] = oacc[dn][3] * inv1;
    }
}

// ---------------------------------------------------------------------------
// K6: output projection (transposed) + bias + residual, f32x2 (unchanged).
// grid = (8 s, 2 c, 16 b)
// ---------------------------------------------------------------------------
__global__ void __launch_bounds__(256) k_oproj(const float* __restrict__ w,
                                               const float* __restrict__ bias,
                                               const float* __restrict__ x,
                                               float* __restrict__ out) {
    __shared__ float As[16][132];   // k x c
    __shared__ float Bs[16][132];   // k x s
    int s0 = blockIdx.x * 128;
    int c0 = blockIdx.y * 128;
    int b  = blockIdx.z;
    int tid = threadIdx.x;
    int tr = tid >> 4, tc = tid & 15;
    u64 acc[8][4];
#pragma unroll
    for (int r = 0; r < 8; r++)
#pragma unroll
        for (int c = 0; c < 4; c++) acc[r][c] = 0ULL;

    for (int k0 = 0; k0 < 256; k0 += 16) {
#pragma unroll
        for (int i = 0; i < 2; i++) {
            int idx = tid + i * 256;
            int row = idx >> 2, kq = idx & 3;
            float4 v = *(const float4*)&w[(c0 + row) * 256 + k0 + kq * 4];
            As[kq * 4 + 0][row] = v.x;
            As[kq * 4 + 1][row] = v.y;
            As[kq * 4 + 2][row] = v.z;
            As[kq * 4 + 3][row] = v.w;
        }
#pragma unroll
        for (int i = 0; i < 2; i++) {
            int idx = tid + i * 256;
            int row = idx >> 2, kq = idx & 3;
            float4 v = *(const float4*)&g_att[(b * 1024 + s0 + row) * 256 + k0 + kq * 4];
            Bs[kq * 4 + 0][row] = v.x;
            Bs[kq * 4 + 1][row] = v.y;
            Bs[kq * 4 + 2][row] = v.z;
            Bs[kq * 4 + 3][row] = v.w;
        }
        __syncthreads();
#pragma unroll
        for (int kk = 0; kk < 16; kk++) {
            F4U a0, a1, b0, b1;
            a0.f = *(const float4*)&As[kk][tr * 4];
            a1.f = *(const float4*)&As[kk][tr * 4 + 64];
            b0.f = *(const float4*)&Bs[kk][tc * 4];
            b1.f = *(const float4*)&Bs[kk][tc * 4 + 64];
            u64 bu[4] = {b0.u[0], b0.u[1], b1.u[0], b1.u[1]};
            float ar[8] = {a0.s[0], a0.s[1], a0.s[2], a0.s[3],
                           a1.s[0], a1.s[1], a1.s[2], a1.s[3]};
#pragma unroll
            for (int r = 0; r < 8; r++) {
                u64 ad = dup2(ar[r]);
#pragma unroll
                for (int c = 0; c < 4; c++) fma2(acc[r][c], ad, bu[c]);
            }
        }
        __syncthreads();
    }

#pragma unroll
    for (int rr = 0; rr < 2; rr++)
#pragma unroll
    for (int r = 0; r < 4; r++) {
        int cg = c0 + tr * 4 + rr * 64 + r;
        u64 bv = dup2(bias[cg]);
#pragma unroll
        for (int cc = 0; cc < 2; cc++) {
            int col = s0 + tc * 4 + cc * 64;
            int idx = (b * 256 + cg) * 1024 + col;
            F4U xr; xr.f = *(const float4*)&x[idx];
            F4U val;
            val.u[0] = add2(add2(acc[rr * 4 + r][cc * 2 + 0], bv), xr.u[0]);
            val.u[1] = add2(add2(acc[rr * 4 + r][cc * 2 + 1], bv), xr.u[1]);
            *(float4*)&out[idx] = val.f;
        }
    }
}

// ---------------------------------------------------------------------------
extern "C" void kernel_launch(void* const* d_in, const int* in_sizes, int n_in,
                              void* d_out, int out_size) {
    const float* x      = (const float*)d_in[0];
    const float* t_emb  = (const float*)d_in[1];
    const float* c_emb  = (const float*)d_in[2];
    const float* gn_w   = (const float*)d_in[3];
    const float* gn_b   = (const float*)d_in[4];
    const float* proj_w = (const float*)d_in[5];
    const float* proj_b = (const float*)d_in[6];
    const float* qkv_w  = (const float*)d_in[7];
    const float* qkv_b  = (const float*)d_in[8];
    const float* out_w  = (const float*)d_in[9];
    const float* out_b  = (const float*)d_in[10];
    float* out = (float*)d_out;

    cudaFuncSetAttribute(k_attn, cudaFuncAttributeMaxDynamicSharedMemorySize,
                         SMEM_ATTN);

    k_adaln<<<16, 640>>>(t_emb, c_emb, proj_w, proj_b);
    k_gnstat<<<128, 256>>>(x);
    k_gnapply<<<dim3(32, 16), 256>>>(x, gn_w, gn_b);
    k_qkv<<<dim3(6, 128), 256>>>(qkv_w, qkv_b);
    k_attn<<<dim3(128, 8), 256, SMEM_ATTN>>>();
    k_oproj<<<dim3(8, 2, 16), 256>>>(out_w, out_b, x, out);
}

// round 9
// speedup vs baseline: 2.3933x; 1.2488x over previous
#include <cuda_runtime.h>
#include <math.h>

// Problem constants
static const int BB   = 16;
static const int CC   = 256;
static const int SS   = 1024;   // 32*32
static const int NH   = 8;
static const int DKk  = 32;
static const int GR   = 8;
static const int TDIM = 512;
static const int CDIM = 128;
static const int INDIM = 640;   // TDIM + CDIM
static const int TWOC = 512;

// ---- tf32 helpers ----
__device__ __forceinline__ unsigned to_tf32(float f) {
    unsigned r; asm("cvt.rna.tf32.f32 %0, %1;" : "=r"(r) : "f"(f)); return r;
}
__device__ __forceinline__ void mma_tf32(float& d0, float& d1, float& d2, float& d3,
                                         unsigned a0, unsigned a1, unsigned a2, unsigned a3,
                                         unsigned b0, unsigned b1) {
    asm("mma.sync.aligned.m16n8k8.row.col.f32.tf32.tf32.f32 "
        "{%0,%1,%2,%3}, {%4,%5,%6,%7}, {%8,%9}, {%0,%1,%2,%3};"
        : "+f"(d0), "+f"(d1), "+f"(d2), "+f"(d3)
        : "r"(a0), "r"(a1), "r"(a2), "r"(a3), "r"(b0), "r"(b1));
}

// Device scratch
__device__ float g_params[BB * TWOC];
__device__ float g_mean[BB * GR];
__device__ float g_rstd[BB * GR];
__device__ float g_xn[BB * SS * CC];
__device__ float g_q[BB * NH * SS * DKk];   // (b,h,s,d)
__device__ float g_k[BB * NH * SS * DKk];
__device__ float g_v[BB * NH * SS * DKk];
__device__ float g_att[BB * SS * CC];       // (b, s, c)

// ---------------------------------------------------------------------------
// K1: adaLN projection. grid = 16, block = 640
// ---------------------------------------------------------------------------
__global__ void k_adaln(const float* __restrict__ t_emb,
                        const float* __restrict__ c_emb,
                        const float* __restrict__ pw,
                        const float* __restrict__ pb) {
    __shared__ float sin_[INDIM];
    int b = blockIdx.x;
    int t = threadIdx.x;
    float v = (t < TDIM) ? t_emb[b * TDIM + t] : c_emb[b * CDIM + (t - TDIM)];
    sin_[t] = v / (1.0f + expf(-v));
    __syncthreads();
    if (t < TWOC) {
        const float* wr = pw + t * INDIM;
        float acc = pb[t];
#pragma unroll 8
        for (int i = 0; i < INDIM; i++) acc += sin_[i] * wr[i];
        g_params[b * TWOC + t] = acc;
    }
}

// ---------------------------------------------------------------------------
// K2: GroupNorm statistics. grid = 128, block = 256
// ---------------------------------------------------------------------------
__global__ void k_gnstat(const float* __restrict__ x) {
    int bg = blockIdx.x;
    const float4* p = (const float4*)(x + (size_t)bg * 32768);
    float s = 0.0f, ss = 0.0f;
    for (int i = threadIdx.x; i < 8192; i += 256) {
        float4 v = p[i];
        s  += v.x + v.y + v.z + v.w;
        ss += v.x * v.x + v.y * v.y + v.z * v.z + v.w * v.w;
    }
#pragma unroll
    for (int o = 16; o; o >>= 1) {
        s  += __shfl_xor_sync(0xffffffffu, s, o);
        ss += __shfl_xor_sync(0xffffffffu, ss, o);
    }
    __shared__ float rs[8], rss[8];
    int w = threadIdx.x >> 5, l = threadIdx.x & 31;
    if (l == 0) { rs[w] = s; rss[w] = ss; }
    __syncthreads();
    if (threadIdx.x == 0) {
        float S = 0.0f, SSum = 0.0f;
#pragma unroll
        for (int i = 0; i < 8; i++) { S += rs[i]; SSum += rss[i]; }
        float m = S / 32768.0f;
        float var = SSum / 32768.0f - m * m;
        g_mean[bg] = m;
        g_rstd[bg] = rsqrtf(var + 1e-6f);
    }
}

// ---------------------------------------------------------------------------
// K3: apply GN + adaLN affine, transpose (b,c,s) -> (b,s,c).
// ---------------------------------------------------------------------------
__global__ void k_gnapply(const float* __restrict__ x,
                          const float* __restrict__ gw,
                          const float* __restrict__ gb) {
    __shared__ float tile[CC][33];
    int b = blockIdx.y;
    int s0 = blockIdx.x * 32;
    int t = threadIdx.x;
    int w = t >> 5, sl = t & 31;
#pragma unroll
    for (int k = 0; k < 32; k++) {
        int c = k * 8 + w;
        float v = x[(b * CC + c) * SS + s0 + sl];
        int g = c >> 5;
        float vn = (v - g_mean[b * GR + g]) * g_rstd[b * GR + g];
        vn = vn * gw[c] + gb[c];
        float gam = g_params[b * TWOC + c];
        float bet = g_params[b * TWOC + CC + c];
        tile[c][sl] = vn * (1.0f + gam) + bet;
    }
    __syncthreads();
#pragma unroll
    for (int k = 0; k < 32; k++) {
        g_xn[(b * SS + s0 + k) * CC + t] = tile[t][k];
    }
}

// ---------------------------------------------------------------------------
// K4: QKV GEMM on tf32 tensor cores.
// C[n,o] = xn[n,:] @ qkv_w[o,:] + qkv_b[o].  M=16384, N=768, K=256.
// Block tile 128x128, 8 warps (4 m x 2 n), warp tile 32x64 (2x8 m16n8 frags).
// K staged in chunks of 32 (stride-36 smem: conflict-free frag loads).
// grid = (6, 128)
// ---------------------------------------------------------------------------
__global__ void __launch_bounds__(256) k_qkv(const float* __restrict__ w,
                                             const float* __restrict__ bias) {
    __shared__ unsigned As[128][36];
    __shared__ unsigned Bs[128][36];
    int m0 = blockIdx.y * 128;
    int o0 = blockIdx.x * 128;
    int tid = threadIdx.x;
    int wid = tid >> 5, lane = tid & 31;
    int gid = lane >> 2, tig = lane & 3;
    int wr = wid & 3, wc = wid >> 2;

    float acc[2][8][4];
#pragma unroll
    for (int mt = 0; mt < 2; mt++)
#pragma unroll
        for (int nt = 0; nt < 8; nt++)
#pragma unroll
            for (int i = 0; i < 4; i++) acc[mt][nt][i] = 0.0f;

    for (int k0 = 0; k0 < 256; k0 += 32) {
        __syncthreads();   // previous chunk's frag reads done
#pragma unroll
        for (int i = 0; i < 4; i++) {
            int idx = tid + i * 256;           // 0..1023
            int row = idx >> 3, q = idx & 7;
            float4 v = *(const float4*)&g_xn[(m0 + row) * 256 + k0 + q * 4];
            uint4 t; t.x = to_tf32(v.x); t.y = to_tf32(v.y);
            t.z = to_tf32(v.z); t.w = to_tf32(v.w);
            *(uint4*)&As[row][q * 4] = t;
            float4 u = *(const float4*)&w[(o0 + row) * 256 + k0 + q * 4];
            uint4 t2; t2.x = to_tf32(u.x); t2.y = to_tf32(u.y);
            t2.z = to_tf32(u.z); t2.w = to_tf32(u.w);
            *(uint4*)&Bs[row][q * 4] = t2;
        }
        __syncthreads();

#pragma unroll
        for (int dk = 0; dk < 4; dk++) {
            unsigned af[2][4];
#pragma unroll
            for (int mt = 0; mt < 2; mt++) {
                int r = wr * 32 + mt * 16 + gid;
                af[mt][0] = As[r][8 * dk + tig];
                af[mt][1] = As[r + 8][8 * dk + tig];
                af[mt][2] = As[r][8 * dk + tig + 4];
                af[mt][3] = As[r + 8][8 * dk + tig + 4];
            }
#pragma unroll
            for (int nt = 0; nt < 8; nt++) {
                int n = wc * 64 + nt * 8 + gid;
                unsigned b0 = Bs[n][8 * dk + tig];
                unsigned b1 = Bs[n][8 * dk + tig + 4];
#pragma unroll
                for (int mt = 0; mt < 2; mt++)
                    mma_tf32(acc[mt][nt][0], acc[mt][nt][1],
                             acc[mt][nt][2], acc[mt][nt][3],
                             af[mt][0], af[mt][1], af[mt][2], af[mt][3], b0, b1);
            }
        }
    }

    // Epilogue: bias + scatter to q/k/v (b,h,s,d)
    float* dst; int obase;
    if (o0 < 256)      { dst = g_q; obase = o0; }
    else if (o0 < 512) { dst = g_k; obase = o0 - 256; }
    else               { dst = g_v; obase = o0 - 512; }
    int b = m0 >> 10;
#pragma unroll
    for (int mt = 0; mt < 2; mt++) {
        int s_0 = (m0 + wr * 32 + mt * 16 + gid) & 1023;
        int s_1 = s_0 + 8;
#pragma unroll
        for (int nt = 0; nt < 8; nt++) {
            int lcol = obase + wc * 64 + nt * 8 + 2 * tig;
            int h = lcol >> 5, d = lcol & 31;
            float bx = bias[o0 - obase + lcol];
            float by = bias[o0 - obase + lcol + 1];
            float2 v0 = make_float2(acc[mt][nt][0] + bx, acc[mt][nt][1] + by);
            float2 v1 = make_float2(acc[mt][nt][2] + bx, acc[mt][nt][3] + by);
            *(float2*)&dst[((b * 8 + h) * 1024 + s_0) * 32 + d] = v0;
            *(float2*)&dst[((b * 8 + h) * 1024 + s_1) * 32 + d] = v1;
        }
    }
}

// ---------------------------------------------------------------------------
// K5: flash attention on tf32 tensor cores (unchanged from R7).
// grid = (128 bh, 8 q-tiles), 256 thr.
// ---------------------------------------------------------------------------
static const int Q_OFF = 0;                 // 128*36
static const int K_OFF = 128 * 36;          // 4608
static const int V_OFF = K_OFF + 128 * 36;  // 9216
static const int P_OFF = V_OFF + 128 * 40;  // 14336
static const int SMEM_ATTN = (P_OFF + 128 * 132) * 4;  // 124928 bytes

__global__ void __launch_bounds__(256, 1) k_attn() {
    extern __shared__ unsigned smu[];
    unsigned (*qs)[36]  = (unsigned(*)[36])(smu + Q_OFF);
    unsigned (*ks)[36]  = (unsigned(*)[36])(smu + K_OFF);
    unsigned (*vs)[40]  = (unsigned(*)[40])(smu + V_OFF);
    unsigned (*ps)[132] = (unsigned(*)[132])(smu + P_OFF);

    int bh = blockIdx.x;
    int m0 = blockIdx.y * 128;
    int tid = threadIdx.x;
    int w = tid >> 5, lane = tid & 31;
    int gid = lane >> 2, tig = lane & 3;
    const float scale = 0.17677669529663687f;   // 1/sqrt(32)
    int base = bh * (1024 * 32);
    int r0 = 16 * w + gid;
    int r1 = r0 + 8;

    // Load Q tile (scaled) as tf32
#pragma unroll
    for (int i = 0; i < 4; i++) {
        int idx = tid + i * 256;
        int row = idx >> 3, dq = idx & 7;
        float4 v = *(const float4*)&g_q[base + (m0 + row) * 32 + dq * 4];
        qs[row][dq * 4 + 0] = to_tf32(v.x * scale);
        qs[row][dq * 4 + 1] = to_tf32(v.y * scale);
        qs[row][dq * 4 + 2] = to_tf32(v.z * scale);
        qs[row][dq * 4 + 3] = to_tf32(v.w * scale);
    }
    __syncthreads();

    unsigned qa[4][4];
#pragma unroll
    for (int dk = 0; dk < 4; dk++) {
        qa[dk][0] = qs[r0][8 * dk + tig];
        qa[dk][1] = qs[r1][8 * dk + tig];
        qa[dk][2] = qs[r0][8 * dk + tig + 4];
        qa[dk][3] = qs[r1][8 * dk + tig + 4];
    }

    float m_0 = -1e30f, m_1 = -1e30f, l_0 = 0.0f, l_1 = 0.0f;
    float oacc[4][4];
#pragma unroll
    for (int dn = 0; dn < 4; dn++)
#pragma unroll
        for (int i = 0; i < 4; i++) oacc[dn][i] = 0.0f;

    for (int j0 = 0; j0 < 1024; j0 += 128) {
        __syncthreads();
#pragma unroll
        for (int i = 0; i < 4; i++) {
            int idx = tid + i * 256;
            int row = idx >> 3, dq = idx & 7;
            float4 kv = *(const float4*)&g_k[base + (j0 + row) * 32 + dq * 4];
            ks[row][dq * 4 + 0] = to_tf32(kv.x);
            ks[row][dq * 4 + 1] = to_tf32(kv.y);
            ks[row][dq * 4 + 2] = to_tf32(kv.z);
            ks[row][dq * 4 + 3] = to_tf32(kv.w);
            float4 vv = *(const float4*)&g_v[base + (j0 + row) * 32 + dq * 4];
            vs[row][dq * 4 + 0] = to_tf32(vv.x);
            vs[row][dq * 4 + 1] = to_tf32(vv.y);
            vs[row][dq * 4 + 2] = to_tf32(vv.z);
            vs[row][dq * 4 + 3] = to_tf32(vv.w);
        }
        __syncthreads();

        // Phase A: S = Q K^T
        float accS[16][4];
#pragma unroll
        for (int jn = 0; jn < 16; jn++) {
            accS[jn][0] = accS[jn][1] = accS[jn][2] = accS[jn][3] = 0.0f;
#pragma unroll
            for (int dk = 0; dk < 4; dk++) {
                unsigned b0 = ks[jn * 8 + gid][8 * dk + tig];
                unsigned b1 = ks[jn * 8 + gid][8 * dk + tig + 4];
                mma_tf32(accS[jn][0], accS[jn][1], accS[jn][2], accS[jn][3],
                         qa[dk][0], qa[dk][1], qa[dk][2], qa[dk][3], b0, b1);
            }
        }

        // Phase B: online softmax
        float mx0 = -1e30f, mx1 = -1e30f;
#pragma unroll
        for (int jn = 0; jn < 16; jn++) {
            mx0 = fmaxf(mx0, fmaxf(accS[jn][0], accS[jn][1]));
            mx1 = fmaxf(mx1, fmaxf(accS[jn][2], accS[jn][3]));
        }
        mx0 = fmaxf(mx0, __shfl_xor_sync(0xffffffffu, mx0, 1));
        mx0 = fmaxf(mx0, __shfl_xor_sync(0xffffffffu, mx0, 2));
        mx1 = fmaxf(mx1, __shfl_xor_sync(0xffffffffu, mx1, 1));
        mx1 = fmaxf(mx1, __shfl_xor_sync(0xffffffffu, mx1, 2));
        float mn0 = fmaxf(m_0, mx0), mn1 = fmaxf(m_1, mx1);
        float corr0 = __expf(m_0 - mn0), corr1 = __expf(m_1 - mn1);
        float sum0 = 0.0f, sum1 = 0.0f;
#pragma unroll
        for (int jn = 0; jn < 16; jn++) {
            float p00 = __expf(accS[jn][0] - mn0);
            float p01 = __expf(accS[jn][1] - mn0);
            float p10 = __expf(accS[jn][2] - mn1);
            float p11 = __expf(accS[jn][3] - mn1);
            sum0 += p00 + p01;
            sum1 += p10 + p11;
            ps[r0][jn * 8 + 2 * tig]     = to_tf32(p00);
            ps[r0][jn * 8 + 2 * tig + 1] = to_tf32(p01);
            ps[r1][jn * 8 + 2 * tig]     = to_tf32(p10);
            ps[r1][jn * 8 + 2 * tig + 1] = to_tf32(p11);
        }
        sum0 += __shfl_xor_sync(0xffffffffu, sum0, 1);
        sum0 += __shfl_xor_sync(0xffffffffu, sum0, 2);
        sum1 += __shfl_xor_sync(0xffffffffu, sum1, 1);
        sum1 += __shfl_xor_sync(0xffffffffu, sum1, 2);
        l_0 = l_0 * corr0 + sum0;
        l_1 = l_1 * corr1 + sum1;
        m_0 = mn0; m_1 = mn1;
#pragma unroll
        for (int dn = 0; dn < 4; dn++) {
            oacc[dn][0] *= corr0; oacc[dn][1] *= corr0;
            oacc[dn][2] *= corr1; oacc[dn][3] *= corr1;
        }
        __syncwarp();

        // Phase C: O += P V
#pragma unroll
        for (int jk = 0; jk < 16; jk++) {
            unsigned pa0 = ps[r0][8 * jk + tig];
            unsigned pa1 = ps[r1][8 * jk + tig];
            unsigned pa2 = ps[r0][8 * jk + tig + 4];
            unsigned pa3 = ps[r1][8 * jk + tig + 4];
#pragma unroll
            for (int dn = 0; dn < 4; dn++) {
                unsigned b0 = vs[8 * jk + tig][8 * dn + gid];
                unsigned b1 = vs[8 * jk + tig + 4][8 * dn + gid];
                mma_tf32(oacc[dn][0], oacc[dn][1], oacc[dn][2], oacc[dn][3],
                         pa0, pa1, pa2, pa3, b0, b1);
            }
        }
        __syncwarp();
    }

    int b = bh >> 3, h = bh & 7;
    float inv0 = 1.0f / l_0, inv1 = 1.0f / l_1;
    int s0g = (b * 1024 + m0 + r0) * 256 + h * 32;
    int s1g = (b * 1024 + m0 + r1) * 256 + h * 32;
#pragma unroll
    for (int dn = 0; dn < 4; dn++) {
        int d = dn * 8 + 2 * tig;
        g_att[s0g + d]     = oacc[dn][0] * inv0;
        g_att[s0g + d + 1] = oacc[dn][1] * inv0;
        g_att[s1g + d]     = oacc[dn][2] * inv1;
        g_att[s1g + d + 1] = oacc[dn][3] * inv1;
    }
}

// ---------------------------------------------------------------------------
// K6: output projection on tf32 tensor cores, transposed output.
// out[b,c,s] = sum_k w[c,k]*att[b,s,k] + bias[c] + x[b,c,s]
// M=c=256 (rows), N=s=1024 (cols), K=256, per batch.
// grid = (8 s-tiles, 2 c-tiles, 16 b)
// ---------------------------------------------------------------------------
__global__ void __launch_bounds__(256) k_oproj(const float* __restrict__ w,
                                               const float* __restrict__ bias,
                                               const float* __restrict__ x,
                                               float* __restrict__ out) {
    __shared__ unsigned As[128][36];   // c rows x k
    __shared__ unsigned Bs[128][36];   // s rows x k
    int s0 = blockIdx.x * 128;
    int c0 = blockIdx.y * 128;
    int b  = blockIdx.z;
    int tid = threadIdx.x;
    int wid = tid >> 5, lane = tid & 31;
    int gid = lane >> 2, tig = lane & 3;
    int wr = wid & 3, wc = wid >> 2;

    float acc[2][8][4];
#pragma unroll
    for (int mt = 0; mt < 2; mt++)
#pragma unroll
        for (int nt = 0; nt < 8; nt++)
#pragma unroll
            for (int i = 0; i < 4; i++) acc[mt][nt][i] = 0.0f;

    for (int k0 = 0; k0 < 256; k0 += 32) {
        __syncthreads();
#pragma unroll
        for (int i = 0; i < 4; i++) {
            int idx = tid + i * 256;
            int row = idx >> 3, q = idx & 7;
            float4 v = *(const float4*)&w[(c0 + row) * 256 + k0 + q * 4];
            uint4 t; t.x = to_tf32(v.x); t.y = to_tf32(v.y);
            t.z = to_tf32(v.z); t.w = to_tf32(v.w);
            *(uint4*)&As[row][q * 4] = t;
            float4 u = *(const float4*)&g_att[(b * 1024 + s0 + row) * 256 + k0 + q * 4];
            uint4 t2; t2.x = to_tf32(u.x); t2.y = to_tf32(u.y);
            t2.z = to_tf32(u.z); t2.w = to_tf32(u.w);
            *(uint4*)&Bs[row][q * 4] = t2;
        }
        __syncthreads();

#pragma unroll
        for (int dk = 0; dk < 4; dk++) {
            unsigned af[2][4];
#pragma unroll
            for (int mt = 0; mt < 2; mt++) {
                int r = wr * 32 + mt * 16 + gid;
                af[mt][0] = As[r][8 * dk + tig];
                af[mt][1] = As[r + 8][8 * dk + tig];
                af[mt][2] = As[r][8 * dk + tig + 4];
                af[mt][3] = As[r + 8][8 * dk + tig + 4];
            }
#pragma unroll
            for (int nt = 0; nt < 8; nt++) {
                int n = wc * 64 + nt * 8 + gid;
                unsigned b0 = Bs[n][8 * dk + tig];
                unsigned b1 = Bs[n][8 * dk + tig + 4];
#pragma unroll
                for (int mt = 0; mt < 2; mt++)
                    mma_tf32(acc[mt][nt][0], acc[mt][nt][1],
                             acc[mt][nt][2], acc[mt][nt][3],
                             af[mt][0], af[mt][1], af[mt][2], af[mt][3], b0, b1);
            }
        }
    }

    // Epilogue: bias + residual, float2 stores along s
#pragma unroll
    for (int mt = 0; mt < 2; mt++) {
        int cg0 = c0 + wr * 32 + mt * 16 + gid;
        int cg1 = cg0 + 8;
        float bv0 = bias[cg0], bv1 = bias[cg1];
#pragma unroll
        for (int nt = 0; nt < 8; nt++) {
            int scol = s0 + wc * 64 + nt * 8 + 2 * tig;
            int idx0 = (b * 256 + cg0) * 1024 + scol;
            int idx1 = (b * 256 + cg1) * 1024 + scol;
            float2 xr0 = *(const float2*)&x[idx0];
            float2 xr1 = *(const float2*)&x[idx1];
            float2 v0 = make_float2(acc[mt][nt][0] + bv0 + xr0.x,
                                    acc[mt][nt][1] + bv0 + xr0.y);
            float2 v1 = make_float2(acc[mt][nt][2] + bv1 + xr1.x,
                                    acc[mt][nt][3] + bv1 + xr1.y);
            *(float2*)&out[idx0] = v0;
            *(float2*)&out[idx1] = v1;
        }
    }
}

// ---------------------------------------------------------------------------
extern "C" void kernel_launch(void* const* d_in, const int* in_sizes, int n_in,
                              void* d_out, int out_size) {
    const float* x      = (const float*)d_in[0];
    const float* t_emb  = (const float*)d_in[1];
    const float* c_emb  = (const float*)d_in[2];
    const float* gn_w   = (const float*)d_in[3];
    const float* gn_b   = (const float*)d_in[4];
    const float* proj_w = (const float*)d_in[5];
    const float* proj_b = (const float*)d_in[6];
    const float* qkv_w  = (const float*)d_in[7];
    const float* qkv_b  = (const float*)d_in[8];
    const float* out_w  = (const float*)d_in[9];
    const float* out_b  = (const float*)d_in[10];
    float* out = (float*)d_out;

    cudaFuncSetAttribute(k_attn, cudaFuncAttributeMaxDynamicSharedMemorySize,
                         SMEM_ATTN);

    k_adaln<<<16, 640>>>(t_emb, c_emb, proj_w, proj_b);
    k_gnstat<<<128, 256>>>(x);
    k_gnapply<<<dim3(32, 16), 256>>>(x, gn_w, gn_b);
    k_qkv<<<dim3(6, 128), 256>>>(qkv_w, qkv_b);
    k_attn<<<dim3(128, 8), 256, SMEM_ATTN>>>();
    k_oproj<<<dim3(8, 2, 16), 256>>>(out_w, out_b, x, out);
}

// round 10
// speedup vs baseline: 3.0955x; 1.2934x over previous
#include <cuda_runtime.h>
#include <math.h>

// Problem constants
static const int BB   = 16;
static const int CC   = 256;
static const int SS   = 1024;   // 32*32
static const int NH   = 8;
static const int DKk  = 32;
static const int GR   = 8;
static const int TDIM = 512;
static const int CDIM = 128;
static const int INDIM = 640;   // TDIM + CDIM
static const int TWOC = 512;

// ---- tf32 / bf16 helpers ----
__device__ __forceinline__ unsigned to_tf32(float f) {
    unsigned r; asm("cvt.rna.tf32.f32 %0, %1;" : "=r"(r) : "f"(f)); return r;
}
// packs {hi, lo} -> bf16x2 register (lo = lower half = first k element)
__device__ __forceinline__ unsigned cvt2(float hi, float lo) {
    unsigned r;
    asm("cvt.rn.bf16x2.f32 %0, %1, %2;" : "=r"(r) : "f"(hi), "f"(lo));
    return r;
}
__device__ __forceinline__ void mma_tf32(float& d0, float& d1, float& d2, float& d3,
                                         unsigned a0, unsigned a1, unsigned a2, unsigned a3,
                                         unsigned b0, unsigned b1) {
    asm("mma.sync.aligned.m16n8k8.row.col.f32.tf32.tf32.f32 "
        "{%0,%1,%2,%3}, {%4,%5,%6,%7}, {%8,%9}, {%0,%1,%2,%3};"
        : "+f"(d0), "+f"(d1), "+f"(d2), "+f"(d3)
        : "r"(a0), "r"(a1), "r"(a2), "r"(a3), "r"(b0), "r"(b1));
}
__device__ __forceinline__ void mma_bf16(float& d0, float& d1, float& d2, float& d3,
                                         unsigned a0, unsigned a1, unsigned a2, unsigned a3,
                                         unsigned b0, unsigned b1) {
    asm("mma.sync.aligned.m16n8k16.row.col.f32.bf16.bf16.f32 "
        "{%0,%1,%2,%3}, {%4,%5,%6,%7}, {%8,%9}, {%0,%1,%2,%3};"
        : "+f"(d0), "+f"(d1), "+f"(d2), "+f"(d3)
        : "r"(a0), "r"(a1), "r"(a2), "r"(a3), "r"(b0), "r"(b1));
}

// Device scratch
__device__ float g_params[BB * TWOC];
__device__ float g_mean[BB * GR];
__device__ float g_rstd[BB * GR];
__device__ float g_xn[BB * SS * CC];
__device__ float g_q[BB * NH * SS * DKk];   // (b,h,s,d)
__device__ float g_k[BB * NH * SS * DKk];
__device__ float g_v[BB * NH * SS * DKk];
__device__ float g_att[BB * SS * CC];       // (b, s, c)

// ---------------------------------------------------------------------------
// K1: adaLN projection. grid = 16, block = 640
// ---------------------------------------------------------------------------
__global__ void k_adaln(const float* __restrict__ t_emb,
                        const float* __restrict__ c_emb,
                        const float* __restrict__ pw,
                        const float* __restrict__ pb) {
    __shared__ float sin_[INDIM];
    int b = blockIdx.x;
    int t = threadIdx.x;
    float v = (t < TDIM) ? t_emb[b * TDIM + t] : c_emb[b * CDIM + (t - TDIM)];
    sin_[t] = v / (1.0f + expf(-v));
    __syncthreads();
    if (t < TWOC) {
        const float* wr = pw + t * INDIM;
        float acc = pb[t];
#pragma unroll 8
        for (int i = 0; i < INDIM; i++) acc += sin_[i] * wr[i];
        g_params[b * TWOC + t] = acc;
    }
}

// ---------------------------------------------------------------------------
// K2: GroupNorm statistics. grid = 128, block = 256
// ---------------------------------------------------------------------------
__global__ void k_gnstat(const float* __restrict__ x) {
    int bg = blockIdx.x;
    const float4* p = (const float4*)(x + (size_t)bg * 32768);
    float s = 0.0f, ss = 0.0f;
    for (int i = threadIdx.x; i < 8192; i += 256) {
        float4 v = p[i];
        s  += v.x + v.y + v.z + v.w;
        ss += v.x * v.x + v.y * v.y + v.z * v.z + v.w * v.w;
    }
#pragma unroll
    for (int o = 16; o; o >>= 1) {
        s  += __shfl_xor_sync(0xffffffffu, s, o);
        ss += __shfl_xor_sync(0xffffffffu, ss, o);
    }
    __shared__ float rs[8], rss[8];
    int w = threadIdx.x >> 5, l = threadIdx.x & 31;
    if (l == 0) { rs[w] = s; rss[w] = ss; }
    __syncthreads();
    if (threadIdx.x == 0) {
        float S = 0.0f, SSum = 0.0f;
#pragma unroll
        for (int i = 0; i < 8; i++) { S += rs[i]; SSum += rss[i]; }
        float m = S / 32768.0f;
        float var = SSum / 32768.0f - m * m;
        g_mean[bg] = m;
        g_rstd[bg] = rsqrtf(var + 1e-6f);
    }
}

// ---------------------------------------------------------------------------
// K3: apply GN + adaLN affine, transpose (b,c,s) -> (b,s,c).
// ---------------------------------------------------------------------------
__global__ void k_gnapply(const float* __restrict__ x,
                          const float* __restrict__ gw,
                          const float* __restrict__ gb) {
    __shared__ float tile[CC][33];
    int b = blockIdx.y;
    int s0 = blockIdx.x * 32;
    int t = threadIdx.x;
    int w = t >> 5, sl = t & 31;
#pragma unroll
    for (int k = 0; k < 32; k++) {
        int c = k * 8 + w;
        float v = x[(b * CC + c) * SS + s0 + sl];
        int g = c >> 5;
        float vn = (v - g_mean[b * GR + g]) * g_rstd[b * GR + g];
        vn = vn * gw[c] + gb[c];
        float gam = g_params[b * TWOC + c];
        float bet = g_params[b * TWOC + CC + c];
        tile[c][sl] = vn * (1.0f + gam) + bet;
    }
    __syncthreads();
#pragma unroll
    for (int k = 0; k < 32; k++) {
        g_xn[(b * SS + s0 + k) * CC + t] = tile[t][k];
    }
}

// ---------------------------------------------------------------------------
// K4: QKV GEMM on bf16 tensor cores (m16n8k16).
// Block tile 128x128, 8 warps (4m x 2n), warp tile 32x64.
// Smem holds bf16x2-packed k-pairs: [row][k2], stride 20 u32 (conflict-free).
// grid = (6, 128)
// ---------------------------------------------------------------------------
__global__ void __launch_bounds__(256) k_qkv(const float* __restrict__ w,
                                             const float* __restrict__ bias) {
    __shared__ unsigned Ap[128][20];
    __shared__ unsigned Bp[128][20];
    int m0 = blockIdx.y * 128;
    int o0 = blockIdx.x * 128;
    int tid = threadIdx.x;
    int wid = tid >> 5, lane = tid & 31;
    int gid = lane >> 2, tig = lane & 3;
    int wr = wid & 3, wc = wid >> 2;

    float acc[2][8][4];
#pragma unroll
    for (int mt = 0; mt < 2; mt++)
#pragma unroll
        for (int nt = 0; nt < 8; nt++)
#pragma unroll
            for (int i = 0; i < 4; i++) acc[mt][nt][i] = 0.0f;

    for (int k0 = 0; k0 < 256; k0 += 32) {
        __syncthreads();
#pragma unroll
        for (int i = 0; i < 4; i++) {
            int idx = tid + i * 256;           // 0..1023
            int row = idx >> 3, q = idx & 7;   // q: float4 index within 32-k chunk
            float4 v = *(const float4*)&g_xn[(m0 + row) * 256 + k0 + q * 4];
            *(uint2*)&Ap[row][2 * q] = make_uint2(cvt2(v.y, v.x), cvt2(v.w, v.z));
            float4 u = *(const float4*)&w[(o0 + row) * 256 + k0 + q * 4];
            *(uint2*)&Bp[row][2 * q] = make_uint2(cvt2(u.y, u.x), cvt2(u.w, u.z));
        }
        __syncthreads();

#pragma unroll
        for (int dk = 0; dk < 2; dk++) {       // two k16 steps per 32-chunk
            unsigned af[2][4];
#pragma unroll
            for (int mt = 0; mt < 2; mt++) {
                int r = wr * 32 + mt * 16 + gid;
                af[mt][0] = Ap[r][8 * dk + tig];
                af[mt][1] = Ap[r + 8][8 * dk + tig];
                af[mt][2] = Ap[r][8 * dk + tig + 4];
                af[mt][3] = Ap[r + 8][8 * dk + tig + 4];
            }
#pragma unroll
            for (int nt = 0; nt < 8; nt++) {
                int n = wc * 64 + nt * 8 + gid;
                unsigned b0 = Bp[n][8 * dk + tig];
                unsigned b1 = Bp[n][8 * dk + tig + 4];
#pragma unroll
                for (int mt = 0; mt < 2; mt++)
                    mma_bf16(acc[mt][nt][0], acc[mt][nt][1],
                             acc[mt][nt][2], acc[mt][nt][3],
                             af[mt][0], af[mt][1], af[mt][2], af[mt][3], b0, b1);
            }
        }
    }

    // Epilogue: bias + scatter to q/k/v (b,h,s,d)
    float* dst; int obase;
    if (o0 < 256)      { dst = g_q; obase = o0; }
    else if (o0 < 512) { dst = g_k; obase = o0 - 256; }
    else               { dst = g_v; obase = o0 - 512; }
    int b = m0 >> 10;
#pragma unroll
    for (int mt = 0; mt < 2; mt++) {
        int s_0 = (m0 + wr * 32 + mt * 16 + gid) & 1023;
        int s_1 = s_0 + 8;
#pragma unroll
        for (int nt = 0; nt < 8; nt++) {
            int lcol = obase + wc * 64 + nt * 8 + 2 * tig;
            int h = lcol >> 5, d = lcol & 31;
            float bx = bias[o0 - obase + lcol];
            float by = bias[o0 - obase + lcol + 1];
            float2 v0 = make_float2(acc[mt][nt][0] + bx, acc[mt][nt][1] + by);
            float2 v1 = make_float2(acc[mt][nt][2] + bx, acc[mt][nt][3] + by);
            *(float2*)&dst[((b * 8 + h) * 1024 + s_0) * 32 + d] = v0;
            *(float2*)&dst[((b * 8 + h) * 1024 + s_1) * 32 + d] = v1;
        }
    }
}

// ---------------------------------------------------------------------------
// K5: flash attention. Phase A (QK^T) tf32, Phase C (P*V) bf16 m16n8k16 with
// P entirely in registers (C-fragment -> A-fragment repack via cvt.bf16x2).
// V staged as bf16x2 j-pairs: vpack[j2][d], stride 40 u32 (conflict-free).
// Static smem: 18KB + 18KB + 10KB = 46KB. grid = (128 bh, 8 q-tiles), 256 thr.
// ---------------------------------------------------------------------------
__global__ void __launch_bounds__(256) k_attn() {
    __shared__ unsigned qs[128][36];     // tf32 Q (scaled)
    __shared__ unsigned ks[128][36];     // tf32 K
    __shared__ unsigned vpack[64][40];   // bf16x2 {V[2j2+1], V[2j2]} at col d

    int bh = blockIdx.x;
    int m0 = blockIdx.y * 128;
    int tid = threadIdx.x;
    int w = tid >> 5, lane = tid & 31;
    int gid = lane >> 2, tig = lane & 3;
    const float scale = 0.17677669529663687f;   // 1/sqrt(32)
    int base = bh * (1024 * 32);
    int r0 = 16 * w + gid;
    int r1 = r0 + 8;

    // Load Q tile (scaled) as tf32
#pragma unroll
    for (int i = 0; i < 4; i++) {
        int idx = tid + i * 256;
        int row = idx >> 3, dq = idx & 7;
        float4 v = *(const float4*)&g_q[base + (m0 + row) * 32 + dq * 4];
        qs[row][dq * 4 + 0] = to_tf32(v.x * scale);
        qs[row][dq * 4 + 1] = to_tf32(v.y * scale);
        qs[row][dq * 4 + 2] = to_tf32(v.z * scale);
        qs[row][dq * 4 + 3] = to_tf32(v.w * scale);
    }
    __syncthreads();

    unsigned qa[4][4];
#pragma unroll
    for (int dk = 0; dk < 4; dk++) {
        qa[dk][0] = qs[r0][8 * dk + tig];
        qa[dk][1] = qs[r1][8 * dk + tig];
        qa[dk][2] = qs[r0][8 * dk + tig + 4];
        qa[dk][3] = qs[r1][8 * dk + tig + 4];
    }

    float m_0 = -1e30f, m_1 = -1e30f, l_0 = 0.0f, l_1 = 0.0f;
    float oacc[4][4];
#pragma unroll
    for (int dn = 0; dn < 4; dn++)
#pragma unroll
        for (int i = 0; i < 4; i++) oacc[dn][i] = 0.0f;

    for (int j0 = 0; j0 < 1024; j0 += 128) {
        __syncthreads();   // previous tile's ks/vpack fully consumed
        // K as tf32
#pragma unroll
        for (int i = 0; i < 4; i++) {
            int idx = tid + i * 256;
            int row = idx >> 3, dq = idx & 7;
            float4 kv = *(const float4*)&g_k[base + (j0 + row) * 32 + dq * 4];
            ks[row][dq * 4 + 0] = to_tf32(kv.x);
            ks[row][dq * 4 + 1] = to_tf32(kv.y);
            ks[row][dq * 4 + 2] = to_tf32(kv.z);
            ks[row][dq * 4 + 3] = to_tf32(kv.w);
        }
        // V as packed bf16 j-pairs: vpack[j2][d] = {hi: V[2j2+1][d], lo: V[2j2][d]}
#pragma unroll
        for (int i = 0; i < 8; i++) {
            int idx = tid + i * 256;           // 0..2047
            int j2 = idx >> 5, d = idx & 31;
            float v0 = g_v[base + (j0 + 2 * j2) * 32 + d];
            float v1 = g_v[base + (j0 + 2 * j2 + 1) * 32 + d];
            vpack[j2][d] = cvt2(v1, v0);
        }
        __syncthreads();

        // Phase A: S = Q K^T (tf32)
        float accS[16][4];
#pragma unroll
        for (int jn = 0; jn < 16; jn++) {
            accS[jn][0] = accS[jn][1] = accS[jn][2] = accS[jn][3] = 0.0f;
#pragma unroll
            for (int dk = 0; dk < 4; dk++) {
                unsigned b0 = ks[jn * 8 + gid][8 * dk + tig];
                unsigned b1 = ks[jn * 8 + gid][8 * dk + tig + 4];
                mma_tf32(accS[jn][0], accS[jn][1], accS[jn][2], accS[jn][3],
                         qa[dk][0], qa[dk][1], qa[dk][2], qa[dk][3], b0, b1);
            }
        }

        // Phase B: online softmax; probabilities written back into accS (fp32)
        float mx0 = -1e30f, mx1 = -1e30f;
#pragma unroll
        for (int jn = 0; jn < 16; jn++) {
            mx0 = fmaxf(mx0, fmaxf(accS[jn][0], accS[jn][1]));
            mx1 = fmaxf(mx1, fmaxf(accS[jn][2], accS[jn][3]));
        }
        mx0 = fmaxf(mx0, __shfl_xor_sync(0xffffffffu, mx0, 1));
        mx0 = fmaxf(mx0, __shfl_xor_sync(0xffffffffu, mx0, 2));
        mx1 = fmaxf(mx1, __shfl_xor_sync(0xffffffffu, mx1, 1));
        mx1 = fmaxf(mx1, __shfl_xor_sync(0xffffffffu, mx1, 2));
        float mn0 = fmaxf(m_0, mx0), mn1 = fmaxf(m_1, mx1);
        float corr0 = __expf(m_0 - mn0), corr1 = __expf(m_1 - mn1);
        float sum0 = 0.0f, sum1 = 0.0f;
#pragma unroll
        for (int jn = 0; jn < 16; jn++) {
            float p00 = __expf(accS[jn][0] - mn0);
            float p01 = __expf(accS[jn][1] - mn0);
            float p10 = __expf(accS[jn][2] - mn1);
            float p11 = __expf(accS[jn][3] - mn1);
            sum0 += p00 + p01;
            sum1 += p10 + p11;
            accS[jn][0] = p00; accS[jn][1] = p01;
            accS[jn][2] = p10; accS[jn][3] = p11;
        }
        sum0 += __shfl_xor_sync(0xffffffffu, sum0, 1);
        sum0 += __shfl_xor_sync(0xffffffffu, sum0, 2);
        sum1 += __shfl_xor_sync(0xffffffffu, sum1, 1);
        sum1 += __shfl_xor_sync(0xffffffffu, sum1, 2);
        l_0 = l_0 * corr0 + sum0;
        l_1 = l_1 * corr1 + sum1;
        m_0 = mn0; m_1 = mn1;
#pragma unroll
        for (int dn = 0; dn < 4; dn++) {
            oacc[dn][0] *= corr0; oacc[dn][1] *= corr0;
            oacc[dn][2] *= corr1; oacc[dn][3] *= corr1;
        }

        // Phase C: O += P V (bf16 m16n8k16, P repacked in registers)
#pragma unroll
        for (int jk = 0; jk < 8; jk++) {
            unsigned a0 = cvt2(accS[2 * jk][1],     accS[2 * jk][0]);
            unsigned a1 = cvt2(accS[2 * jk][3],     accS[2 * jk][2]);
            unsigned a2 = cvt2(accS[2 * jk + 1][1], accS[2 * jk + 1][0]);
            unsigned a3 = cvt2(accS[2 * jk + 1][3], accS[2 * jk + 1][2]);
#pragma unroll
            for (int dn = 0; dn < 4; dn++) {
                unsigned b0 = vpack[8 * jk + tig][8 * dn + gid];
                unsigned b1 = vpack[8 * jk + tig + 4][8 * dn + gid];
                mma_bf16(oacc[dn][0], oacc[dn][1], oacc[dn][2], oacc[dn][3],
                         a0, a1, a2, a3, b0, b1);
            }
        }
    }

    // Epilogue: normalize, write (b, s, c = h*32 + d)
    int b = bh >> 3, h = bh & 7;
    float inv0 = 1.0f / l_0, inv1 = 1.0f / l_1;
    int s0g = (b * 1024 + m0 + r0) * 256 + h * 32;
    int s1g = (b * 1024 + m0 + r1) * 256 + h * 32;
#pragma unroll
    for (int dn = 0; dn < 4; dn++) {
        int d = dn * 8 + 2 * tig;
        g_att[s0g + d]     = oacc[dn][0] * inv0;
        g_att[s0g + d + 1] = oacc[dn][1] * inv0;
        g_att[s1g + d]     = oacc[dn][2] * inv1;
        g_att[s1g + d + 1] = oacc[dn][3] * inv1;
    }
}

// ---------------------------------------------------------------------------
// K6: output projection on bf16 tensor cores, transposed output.
// out[b,c,s] = sum_k w[c,k]*att[b,s,k] + bias[c] + x[b,c,s]
// grid = (8 s-tiles, 2 c-tiles, 16 b)
// ---------------------------------------------------------------------------
__global__ void __launch_bounds__(256) k_oproj(const float* __restrict__ w,
                                               const float* __restrict__ bias,
                                               const float* __restrict__ x,
                                               float* __restrict__ out) {
    __shared__ unsigned Ap[128][20];   // c rows x k2
    __shared__ unsigned Bp[128][20];   // s rows x k2
    int s0 = blockIdx.x * 128;
    int c0 = blockIdx.y * 128;
    int b  = blockIdx.z;
    int tid = threadIdx.x;
    int wid = tid >> 5, lane = tid & 31;
    int gid = lane >> 2, tig = lane & 3;
    int wr = wid & 3, wc = wid >> 2;

    float acc[2][8][4];
#pragma unroll
    for (int mt = 0; mt < 2; mt++)
#pragma unroll
        for (int nt = 0; nt < 8; nt++)
#pragma unroll
            for (int i = 0; i < 4; i++) acc[mt][nt][i] = 0.0f;

    for (int k0 = 0; k0 < 256; k0 += 32) {
        __syncthreads();
#pragma unroll
        for (int i = 0; i < 4; i++) {
            int idx = tid + i * 256;
            int row = idx >> 3, q = idx & 7;
            float4 v = *(const float4*)&w[(c0 + row) * 256 + k0 + q * 4];
            *(uint2*)&Ap[row][2 * q] = make_uint2(cvt2(v.y, v.x), cvt2(v.w, v.z));
            float4 u = *(const float4*)&g_att[(b * 1024 + s0 + row) * 256 + k0 + q * 4];
            *(uint2*)&Bp[row][2 * q] = make_uint2(cvt2(u.y, u.x), cvt2(u.w, u.z));
        }
        __syncthreads();

#pragma unroll
        for (int dk = 0; dk < 2; dk++) {
            unsigned af[2][4];
#pragma unroll
            for (int mt = 0; mt < 2; mt++) {
                int r = wr * 32 + mt * 16 + gid;
                af[mt][0] = Ap[r][8 * dk + tig];
                af[mt][1] = Ap[r + 8][8 * dk + tig];
                af[mt][2] = Ap[r][8 * dk + tig + 4];
                af[mt][3] = Ap[r + 8][8 * dk + tig + 4];
            }
#pragma unroll
            for (int nt = 0; nt < 8; nt++) {
                int n = wc * 64 + nt * 8 + gid;
                unsigned b0 = Bp[n][8 * dk + tig];
                unsigned b1 = Bp[n][8 * dk + tig + 4];
#pragma unroll
                for (int mt = 0; mt < 2; mt++)
                    mma_bf16(acc[mt][nt][0], acc[mt][nt][1],
                             acc[mt][nt][2], acc[mt][nt][3],
                             af[mt][0], af[mt][1], af[mt][2], af[mt][3], b0, b1);
            }
        }
    }

    // Epilogue: bias + residual, float2 stores along s
#pragma unroll
    for (int mt = 0; mt < 2; mt++) {
        int cg0 = c0 + wr * 32 + mt * 16 + gid;
        int cg1 = cg0 + 8;
        float bv0 = bias[cg0], bv1 = bias[cg1];
#pragma unroll
        for (int nt = 0; nt < 8; nt++) {
            int scol = s0 + wc * 64 + nt * 8 + 2 * tig;
            int idx0 = (b * 256 + cg0) * 1024 + scol;
            int idx1 = (b * 256 + cg1) * 1024 + scol;
            float2 xr0 = *(const float2*)&x[idx0];
            float2 xr1 = *(const float2*)&x[idx1];
            float2 v0 = make_float2(acc[mt][nt][0] + bv0 + xr0.x,
                                    acc[mt][nt][1] + bv0 + xr0.y);
            float2 v1 = make_float2(acc[mt][nt][2] + bv1 + xr1.x,
                                    acc[mt][nt][3] + bv1 + xr1.y);
            *(float2*)&out[idx0] = v0;
            *(float2*)&out[idx1] = v1;
        }
    }
}

// ---------------------------------------------------------------------------
extern "C" void kernel_launch(void* const* d_in, const int* in_sizes, int n_in,
                              void* d_out, int out_size) {
    const float* x      = (const float*)d_in[0];
    const float* t_emb  = (const float*)d_in[1];
    const float* c_emb  = (const float*)d_in[2];
    const float* gn_w   = (const float*)d_in[3];
    const float* gn_b   = (const float*)d_in[4];
    const float* proj_w = (const float*)d_in[5];
    const float* proj_b = (const float*)d_in[6];
    const float* qkv_w  = (const float*)d_in[7];
    const float* qkv_b  = (const float*)d_in[8];
    const float* out_w  = (const float*)d_in[9];
    const float* out_b  = (const float*)d_in[10];
    float* out = (float*)d_out;

    k_adaln<<<16, 640>>>(t_emb, c_emb, proj_w, proj_b);
    k_gnstat<<<128, 256>>>(x);
    k_gnapply<<<dim3(32, 16), 256>>>(x, gn_w, gn_b);
    k_qkv<<<dim3(6, 128), 256>>>(qkv_w, qkv_b);
    k_attn<<<dim3(128, 8), 256>>>();
    k_oproj<<<dim3(8, 2, 16), 256>>>(out_w, out_b, x, out);
}

// round 11
// speedup vs baseline: 3.2168x; 1.0392x over previous
#include <cuda_runtime.h>
#include <math.h>

// Problem constants
static const int BB   = 16;
static const int CC   = 256;
static const int SS   = 1024;   // 32*32
static const int NH   = 8;
static const int DKk  = 32;
static const int GR   = 8;
static const int TDIM = 512;
static const int CDIM = 128;
static const int INDIM = 640;   // TDIM + CDIM
static const int TWOC = 512;

// ---- tf32 / bf16 / ldmatrix helpers ----
__device__ __forceinline__ unsigned to_tf32(float f) {
    unsigned r; asm("cvt.rna.tf32.f32 %0, %1;" : "=r"(r) : "f"(f)); return r;
}
// packs {hi, lo} -> bf16x2 register (lo = lower half = first k element)
__device__ __forceinline__ unsigned cvt2(float hi, float lo) {
    unsigned r;
    asm("cvt.rn.bf16x2.f32 %0, %1, %2;" : "=r"(r) : "f"(hi), "f"(lo));
    return r;
}
__device__ __forceinline__ float ex2f(float x) {
    float y; asm("ex2.approx.ftz.f32 %0, %1;" : "=f"(y) : "f"(x)); return y;
}
__device__ __forceinline__ unsigned s2u(const void* p) {
    return (unsigned)__cvta_generic_to_shared(p);
}
__device__ __forceinline__ void ldsm4(unsigned& r0, unsigned& r1,
                                      unsigned& r2, unsigned& r3, unsigned a) {
    asm volatile("ldmatrix.sync.aligned.m8n8.x4.shared.b16 {%0,%1,%2,%3}, [%4];"
                 : "=r"(r0), "=r"(r1), "=r"(r2), "=r"(r3) : "r"(a));
}
__device__ __forceinline__ void mma_tf32(float& d0, float& d1, float& d2, float& d3,
                                         unsigned a0, unsigned a1, unsigned a2, unsigned a3,
                                         unsigned b0, unsigned b1) {
    asm("mma.sync.aligned.m16n8k8.row.col.f32.tf32.tf32.f32 "
        "{%0,%1,%2,%3}, {%4,%5,%6,%7}, {%8,%9}, {%0,%1,%2,%3};"
        : "+f"(d0), "+f"(d1), "+f"(d2), "+f"(d3)
        : "r"(a0), "r"(a1), "r"(a2), "r"(a3), "r"(b0), "r"(b1));
}
__device__ __forceinline__ void mma_bf16(float& d0, float& d1, float& d2, float& d3,
                                         unsigned a0, unsigned a1, unsigned a2, unsigned a3,
                                         unsigned b0, unsigned b1) {
    asm("mma.sync.aligned.m16n8k16.row.col.f32.bf16.bf16.f32 "
        "{%0,%1,%2,%3}, {%4,%5,%6,%7}, {%8,%9}, {%0,%1,%2,%3};"
        : "+f"(d0), "+f"(d1), "+f"(d2), "+f"(d3)
        : "r"(a0), "r"(a1), "r"(a2), "r"(a3), "r"(b0), "r"(b1));
}

// Device scratch
__device__ float g_params[BB * TWOC];
__device__ float g_mean[BB * GR];
__device__ float g_rstd[BB * GR];
__device__ float g_xn[BB * SS * CC];
__device__ float g_q[BB * NH * SS * DKk];   // (b,h,s,d)
__device__ float g_k[BB * NH * SS * DKk];
__device__ float g_v[BB * NH * SS * DKk];
__device__ float g_att[BB * SS * CC];       // (b, s, c)

// ---------------------------------------------------------------------------
// K1: adaLN projection. grid = 16, block = 640
// ---------------------------------------------------------------------------
__global__ void k_adaln(const float* __restrict__ t_emb,
                        const float* __restrict__ c_emb,
                        const float* __restrict__ pw,
                        const float* __restrict__ pb) {
    __shared__ float sin_[INDIM];
    int b = blockIdx.x;
    int t = threadIdx.x;
    float v = (t < TDIM) ? t_emb[b * TDIM + t] : c_emb[b * CDIM + (t - TDIM)];
    sin_[t] = v / (1.0f + expf(-v));
    __syncthreads();
    if (t < TWOC) {
        const float* wr = pw + t * INDIM;
        float acc = pb[t];
#pragma unroll 8
        for (int i = 0; i < INDIM; i++) acc += sin_[i] * wr[i];
        g_params[b * TWOC + t] = acc;
    }
}

// ---------------------------------------------------------------------------
// K2: GroupNorm statistics. grid = 128, block = 256
// ---------------------------------------------------------------------------
__global__ void k_gnstat(const float* __restrict__ x) {
    int bg = blockIdx.x;
    const float4* p = (const float4*)(x + (size_t)bg * 32768);
    float s = 0.0f, ss = 0.0f;
    for (int i = threadIdx.x; i < 8192; i += 256) {
        float4 v = p[i];
        s  += v.x + v.y + v.z + v.w;
        ss += v.x * v.x + v.y * v.y + v.z * v.z + v.w * v.w;
    }
#pragma unroll
    for (int o = 16; o; o >>= 1) {
        s  += __shfl_xor_sync(0xffffffffu, s, o);
        ss += __shfl_xor_sync(0xffffffffu, ss, o);
    }
    __shared__ float rs[8], rss[8];
    int w = threadIdx.x >> 5, l = threadIdx.x & 31;
    if (l == 0) { rs[w] = s; rss[w] = ss; }
    __syncthreads();
    if (threadIdx.x == 0) {
        float S = 0.0f, SSum = 0.0f;
#pragma unroll
        for (int i = 0; i < 8; i++) { S += rs[i]; SSum += rss[i]; }
        float m = S / 32768.0f;
        float var = SSum / 32768.0f - m * m;
        g_mean[bg] = m;
        g_rstd[bg] = rsqrtf(var + 1e-6f);
    }
}

// ---------------------------------------------------------------------------
// K3: apply GN + adaLN affine, transpose (b,c,s) -> (b,s,c).
// ---------------------------------------------------------------------------
__global__ void k_gnapply(const float* __restrict__ x,
                          const float* __restrict__ gw,
                          const float* __restrict__ gb) {
    __shared__ float tile[CC][33];
    int b = blockIdx.y;
    int s0 = blockIdx.x * 32;
    int t = threadIdx.x;
    int w = t >> 5, sl = t & 31;
#pragma unroll
    for (int k = 0; k < 32; k++) {
        int c = k * 8 + w;
        float v = x[(b * CC + c) * SS + s0 + sl];
        int g = c >> 5;
        float vn = (v - g_mean[b * GR + g]) * g_rstd[b * GR + g];
        vn = vn * gw[c] + gb[c];
        float gam = g_params[b * TWOC + c];
        float bet = g_params[b * TWOC + CC + c];
        tile[c][sl] = vn * (1.0f + gam) + bet;
    }
    __syncthreads();
#pragma unroll
    for (int k = 0; k < 32; k++) {
        g_xn[(b * SS + s0 + k) * CC + t] = tile[t][k];
    }
}

// ---------------------------------------------------------------------------
// K4: QKV GEMM, bf16 m16n8k16 with ldmatrix.x4 fragment loads.
// Block tile 128x128, 8 warps (4m x 2n), warp tile 32x64. grid = (6, 128)
// ---------------------------------------------------------------------------
__global__ void __launch_bounds__(256) k_qkv(const float* __restrict__ w,
                                             const float* __restrict__ bias) {
    __shared__ unsigned Ap[128][20];
    __shared__ unsigned Bp[128][20];
    int m0 = blockIdx.y * 128;
    int o0 = blockIdx.x * 128;
    int tid = threadIdx.x;
    int wid = tid >> 5, lane = tid & 31;
    int gid = lane >> 2, tig = lane & 3;
    int wr = wid & 3, wc = wid >> 2;
    int lm = lane >> 3, lr = lane & 7;

    unsigned aBase = s2u(&Ap[0][0]);
    unsigned bBase = s2u(&Bp[0][0]);
    int aRow = wr * 32 + (lm & 1) * 8 + lr;   // + mt*16
    int aCol = 4 * (lm >> 1);
    int bRow = wc * 64 + (lm >> 1) * 8 + lr;  // + np*16
    int bCol = 4 * (lm & 1);

    float acc[2][8][4];
#pragma unroll
    for (int mt = 0; mt < 2; mt++)
#pragma unroll
        for (int nt = 0; nt < 8; nt++)
#pragma unroll
            for (int i = 0; i < 4; i++) acc[mt][nt][i] = 0.0f;

    for (int k0 = 0; k0 < 256; k0 += 32) {
        __syncthreads();
#pragma unroll
        for (int i = 0; i < 4; i++) {
            int idx = tid + i * 256;           // 0..1023
            int row = idx >> 3, q = idx & 7;
            float4 v = *(const float4*)&g_xn[(m0 + row) * 256 + k0 + q * 4];
            *(uint2*)&Ap[row][2 * q] = make_uint2(cvt2(v.y, v.x), cvt2(v.w, v.z));
            float4 u = *(const float4*)&w[(o0 + row) * 256 + k0 + q * 4];
            *(uint2*)&Bp[row][2 * q] = make_uint2(cvt2(u.y, u.x), cvt2(u.w, u.z));
        }
        __syncthreads();

#pragma unroll
        for (int dk = 0; dk < 2; dk++) {
            unsigned af[2][4];
#pragma unroll
            for (int mt = 0; mt < 2; mt++)
                ldsm4(af[mt][0], af[mt][1], af[mt][2], af[mt][3],
                      aBase + 4u * ((aRow + mt * 16) * 20 + 8 * dk + aCol));
#pragma unroll
            for (int np = 0; np < 4; np++) {
                unsigned b0a, b1a, b0b, b1b;
                ldsm4(b0a, b1a, b0b, b1b,
                      bBase + 4u * ((bRow + np * 16) * 20 + 8 * dk + bCol));
#pragma unroll
                for (int mt = 0; mt < 2; mt++) {
                    mma_bf16(acc[mt][2 * np][0], acc[mt][2 * np][1],
                             acc[mt][2 * np][2], acc[mt][2 * np][3],
                             af[mt][0], af[mt][1], af[mt][2], af[mt][3], b0a, b1a);
                    mma_bf16(acc[mt][2 * np + 1][0], acc[mt][2 * np + 1][1],
                             acc[mt][2 * np + 1][2], acc[mt][2 * np + 1][3],
                             af[mt][0], af[mt][1], af[mt][2], af[mt][3], b0b, b1b);
                }
            }
        }
    }

    // Epilogue: bias + scatter to q/k/v (b,h,s,d)
    float* dst; int obase;
    if (o0 < 256)      { dst = g_q; obase = o0; }
    else if (o0 < 512) { dst = g_k; obase = o0 - 256; }
    else               { dst = g_v; obase = o0 - 512; }
    int b = m0 >> 10;
#pragma unroll
    for (int mt = 0; mt < 2; mt++) {
        int s_0 = (m0 + wr * 32 + mt * 16 + gid) & 1023;
        int s_1 = s_0 + 8;
#pragma unroll
        for (int nt = 0; nt < 8; nt++) {
            int lcol = obase + wc * 64 + nt * 8 + 2 * tig;
            int h = lcol >> 5, d = lcol & 31;
            float bx = bias[o0 - obase + lcol];
            float by = bias[o0 - obase + lcol + 1];
            float2 v0 = make_float2(acc[mt][nt][0] + bx, acc[mt][nt][1] + by);
            float2 v1 = make_float2(acc[mt][nt][2] + bx, acc[mt][nt][3] + by);
            *(float2*)&dst[((b * 8 + h) * 1024 + s_0) * 32 + d] = v0;
            *(float2*)&dst[((b * 8 + h) * 1024 + s_1) * 32 + d] = v1;
        }
    }
}

// ---------------------------------------------------------------------------
// K5: flash attention. Phase A tf32 + ldmatrix.x4, base-2 softmax (ex2),
// Phase C bf16 with register P; V staged via float4 + STS.128.
// grid = (128 bh, 8 q-tiles), 256 thr, 46KB static smem.
// ---------------------------------------------------------------------------
__global__ void __launch_bounds__(256) k_attn() {
    __shared__ unsigned qs[128][36];     // tf32 Q (scaled by 1/sqrt(d)*log2e)
    __shared__ unsigned ks[128][36];     // tf32 K
    __shared__ unsigned vpack[64][40];   // bf16x2 {V[2j2+1], V[2j2]} at col d

    int bh = blockIdx.x;
    int m0 = blockIdx.y * 128;
    int tid = threadIdx.x;
    int w = tid >> 5, lane = tid & 31;
    int gid = lane >> 2, tig = lane & 3;
    int lm = lane >> 3, lr = lane & 7;
    // 1/sqrt(32) * log2(e): softmax computed in base 2
    const float scale = 0.17677669529663687f * 1.4426950408889634f;
    int base = bh * (1024 * 32);
    int r0 = 16 * w + gid;
    int r1 = r0 + 8;

    unsigned ksBase = s2u(&ks[0][0]);
    int kRow = 8 * (lm >> 1) + lr;   // + 16*jp
    int kCol = 4 * (lm & 1);

    // Load Q tile (scaled) as tf32
#pragma unroll
    for (int i = 0; i < 4; i++) {
        int idx = tid + i * 256;
        int row = idx >> 3, dq = idx & 7;
        float4 v = *(const float4*)&g_q[base + (m0 + row) * 32 + dq * 4];
        qs[row][dq * 4 + 0] = to_tf32(v.x * scale);
        qs[row][dq * 4 + 1] = to_tf32(v.y * scale);
        qs[row][dq * 4 + 2] = to_tf32(v.z * scale);
        qs[row][dq * 4 + 3] = to_tf32(v.w * scale);
    }
    __syncthreads();

    unsigned qa[4][4];
#pragma unroll
    for (int dk = 0; dk < 4; dk++) {
        qa[dk][0] = qs[r0][8 * dk + tig];
        qa[dk][1] = qs[r1][8 * dk + tig];
        qa[dk][2] = qs[r0][8 * dk + tig + 4];
        qa[dk][3] = qs[r1][8 * dk + tig + 4];
    }

    float m_0 = -1e30f, m_1 = -1e30f, l_0 = 0.0f, l_1 = 0.0f;
    float oacc[4][4];
#pragma unroll
    for (int dn = 0; dn < 4; dn++)
#pragma unroll
        for (int i = 0; i < 4; i++) oacc[dn][i] = 0.0f;

    for (int j0 = 0; j0 < 1024; j0 += 128) {
        __syncthreads();   // previous tile's ks/vpack fully consumed
        // K as tf32
#pragma unroll
        for (int i = 0; i < 4; i++) {
            int idx = tid + i * 256;
            int row = idx >> 3, dq = idx & 7;
            float4 kv = *(const float4*)&g_k[base + (j0 + row) * 32 + dq * 4];
            ks[row][dq * 4 + 0] = to_tf32(kv.x);
            ks[row][dq * 4 + 1] = to_tf32(kv.y);
            ks[row][dq * 4 + 2] = to_tf32(kv.z);
            ks[row][dq * 4 + 3] = to_tf32(kv.w);
        }
        // V as packed bf16 j-pairs via float4 loads + STS.128
#pragma unroll
        for (int i = 0; i < 2; i++) {
            int item = tid + i * 256;          // 0..511
            int j2 = item >> 3, dq = item & 7;
            float4 v0 = *(const float4*)&g_v[base + (j0 + 2 * j2) * 32 + dq * 4];
            float4 v1 = *(const float4*)&g_v[base + (j0 + 2 * j2 + 1) * 32 + dq * 4];
            uint4 pk;
            pk.x = cvt2(v1.x, v0.x); pk.y = cvt2(v1.y, v0.y);
            pk.z = cvt2(v1.z, v0.z); pk.w = cvt2(v1.w, v0.w);
            *(uint4*)&vpack[j2][dq * 4] = pk;
        }
        __syncthreads();

        // Phase A: S = Q K^T (tf32, ldmatrix K fragments)
        float accS[16][4];
#pragma unroll
        for (int jp = 0; jp < 8; jp++) {
            int ja = 2 * jp, jb = 2 * jp + 1;
            accS[ja][0] = accS[ja][1] = accS[ja][2] = accS[ja][3] = 0.0f;
            accS[jb][0] = accS[jb][1] = accS[jb][2] = accS[jb][3] = 0.0f;
#pragma unroll
            for (int dk = 0; dk < 4; dk++) {
                unsigned b0a, b1a, b0b, b1b;
                ldsm4(b0a, b1a, b0b, b1b,
                      ksBase + 4u * ((16 * jp + kRow) * 36 + 8 * dk + kCol));
                mma_tf32(accS[ja][0], accS[ja][1], accS[ja][2], accS[ja][3],
                         qa[dk][0], qa[dk][1], qa[dk][2], qa[dk][3], b0a, b1a);
                mma_tf32(accS[jb][0], accS[jb][1], accS[jb][2], accS[jb][3],
                         qa[dk][0], qa[dk][1], qa[dk][2], qa[dk][3], b0b, b1b);
            }
        }

        // Phase B: online softmax, base 2 (scores already carry log2e)
        float mx0 = -1e30f, mx1 = -1e30f;
#pragma unroll
        for (int jn = 0; jn < 16; jn++) {
            mx0 = fmaxf(mx0, fmaxf(accS[jn][0], accS[jn][1]));
            mx1 = fmaxf(mx1, fmaxf(accS[jn][2], accS[jn][3]));
        }
        mx0 = fmaxf(mx0, __shfl_xor_sync(0xffffffffu, mx0, 1));
        mx0 = fmaxf(mx0, __shfl_xor_sync(0xffffffffu, mx0, 2));
        mx1 = fmaxf(mx1, __shfl_xor_sync(0xffffffffu, mx1, 1));
        mx1 = fmaxf(mx1, __shfl_xor_sync(0xffffffffu, mx1, 2));
        float mn0 = fmaxf(m_0, mx0), mn1 = fmaxf(m_1, mx1);
        float corr0 = ex2f(m_0 - mn0), corr1 = ex2f(m_1 - mn1);
        float sum0 = 0.0f, sum1 = 0.0f;
#pragma unroll
        for (int jn = 0; jn < 16; jn++) {
            float p00 = ex2f(accS[jn][0] - mn0);
            float p01 = ex2f(accS[jn][1] - mn0);
            float p10 = ex2f(accS[jn][2] - mn1);
            float p11 = ex2f(accS[jn][3] - mn1);
            sum0 += p00 + p01;
            sum1 += p10 + p11;
            accS[jn][0] = p00; accS[jn][1] = p01;
            accS[jn][2] = p10; accS[jn][3] = p11;
        }
        sum0 += __shfl_xor_sync(0xffffffffu, sum0, 1);
        sum0 += __shfl_xor_sync(0xffffffffu, sum0, 2);
        sum1 += __shfl_xor_sync(0xffffffffu, sum1, 1);
        sum1 += __shfl_xor_sync(0xffffffffu, sum1, 2);
        l_0 = l_0 * corr0 + sum0;
        l_1 = l_1 * corr1 + sum1;
        m_0 = mn0; m_1 = mn1;
#pragma unroll
        for (int dn = 0; dn < 4; dn++) {
            oacc[dn][0] *= corr0; oacc[dn][1] *= corr0;
            oacc[dn][2] *= corr1; oacc[dn][3] *= corr1;
        }

        // Phase C: O += P V (bf16 m16n8k16, P repacked in registers)
#pragma unroll
        for (int jk = 0; jk < 8; jk++) {
            unsigned a0 = cvt2(accS[2 * jk][1],     accS[2 * jk][0]);
            unsigned a1 = cvt2(accS[2 * jk][3],     accS[2 * jk][2]);
            unsigned a2 = cvt2(accS[2 * jk + 1][1], accS[2 * jk + 1][0]);
            unsigned a3 = cvt2(accS[2 * jk + 1][3], accS[2 * jk + 1][2]);
#pragma unroll
            for (int dn = 0; dn < 4; dn++) {
                unsigned b0 = vpack[8 * jk + tig][8 * dn + gid];
                unsigned b1 = vpack[8 * jk + tig + 4][8 * dn + gid];
                mma_bf16(oacc[dn][0], oacc[dn][1], oacc[dn][2], oacc[dn][3],
                         a0, a1, a2, a3, b0, b1);
            }
        }
    }

    // Epilogue: normalize, write (b, s, c = h*32 + d)
    int b = bh >> 3, h = bh & 7;
    float inv0 = 1.0f / l_0, inv1 = 1.0f / l_1;
    int s0g = (b * 1024 + m0 + r0) * 256 + h * 32;
    int s1g = (b * 1024 + m0 + r1) * 256 + h * 32;
#pragma unroll
    for (int dn = 0; dn < 4; dn++) {
        int d = dn * 8 + 2 * tig;
        g_att[s0g + d]     = oacc[dn][0] * inv0;
        g_att[s0g + d + 1] = oacc[dn][1] * inv0;
        g_att[s1g + d]     = oacc[dn][2] * inv1;
        g_att[s1g + d + 1] = oacc[dn][3] * inv1;
    }
}

// ---------------------------------------------------------------------------
// K6: output projection, bf16 m16n8k16 + ldmatrix, transposed output.
// grid = (8 s-tiles, 2 c-tiles, 16 b)
// ---------------------------------------------------------------------------
__global__ void __launch_bounds__(256) k_oproj(const float* __restrict__ w,
                                               const float* __restrict__ bias,
                                               const float* __restrict__ x,
                                               float* __restrict__ out) {
    __shared__ unsigned Ap[128][20];   // c rows x k2
    __shared__ unsigned Bp[128][20];   // s rows x k2
    int s0 = blockIdx.x * 128;
    int c0 = blockIdx.y * 128;
    int b  = blockIdx.z;
    int tid = threadIdx.x;
    int wid = tid >> 5, lane = tid & 31;
    int gid = lane >> 2, tig = lane & 3;
    int wr = wid & 3, wc = wid >> 2;
    int lm = lane >> 3, lr = lane & 7;

    unsigned aBase = s2u(&Ap[0][0]);
    unsigned bBase = s2u(&Bp[0][0]);
    int aRow = wr * 32 + (lm & 1) * 8 + lr;
    int aCol = 4 * (lm >> 1);
    int bRow = wc * 64 + (lm >> 1) * 8 + lr;
    int bCol = 4 * (lm & 1);

    float acc[2][8][4];
#pragma unroll
    for (int mt = 0; mt < 2; mt++)
#pragma unroll
        for (int nt = 0; nt < 8; nt++)
#pragma unroll
            for (int i = 0; i < 4; i++) acc[mt][nt][i] = 0.0f;

    for (int k0 = 0; k0 < 256; k0 += 32) {
        __syncthreads();
#pragma unroll
        for (int i = 0; i < 4; i++) {
            int idx = tid + i * 256;
            int row = idx >> 3, q = idx & 7;
            float4 v = *(const float4*)&w[(c0 + row) * 256 + k0 + q * 4];
            *(uint2*)&Ap[row][2 * q] = make_uint2(cvt2(v.y, v.x), cvt2(v.w, v.z));
            float4 u = *(const float4*)&g_att[(b * 1024 + s0 + row) * 256 + k0 + q * 4];
            *(uint2*)&Bp[row][2 * q] = make_uint2(cvt2(u.y, u.x), cvt2(u.w, u.z));
        }
        __syncthreads();

#pragma unroll
        for (int dk = 0; dk < 2; dk++) {
            unsigned af[2][4];
#pragma unroll
            for (int mt = 0; mt < 2; mt++)
                ldsm4(af[mt][0], af[mt][1], af[mt][2], af[mt][3],
                      aBase + 4u * ((aRow + mt * 16) * 20 + 8 * dk + aCol));
#pragma unroll
            for (int np = 0; np < 4; np++) {
                unsigned b0a, b1a, b0b, b1b;
                ldsm4(b0a, b1a, b0b, b1b,
                      bBase + 4u * ((bRow + np * 16) * 20 + 8 * dk + bCol));
#pragma unroll
                for (int mt = 0; mt < 2; mt++) {
                    mma_bf16(acc[mt][2 * np][0], acc[mt][2 * np][1],
                             acc[mt][2 * np][2], acc[mt][2 * np][3],
                             af[mt][0], af[mt][1], af[mt][2], af[mt][3], b0a, b1a);
                    mma_bf16(acc[mt][2 * np + 1][0], acc[mt][2 * np + 1][1],
                             acc[mt][2 * np + 1][2], acc[mt][2 * np + 1][3],
                             af[mt][0], af[mt][1], af[mt][2], af[mt][3], b0b, b1b);
                }
            }
        }
    }

    // Epilogue: bias + residual, float2 stores along s
#pragma unroll
    for (int mt = 0; mt < 2; mt++) {
        int cg0 = c0 + wr * 32 + mt * 16 + gid;
        int cg1 = cg0 + 8;
        float bv0 = bias[cg0], bv1 = bias[cg1];
#pragma unroll
        for (int nt = 0; nt < 8; nt++) {
            int scol = s0 + wc * 64 + nt * 8 + 2 * tig;
            int idx0 = (b * 256 + cg0) * 1024 + scol;
            int idx1 = (b * 256 + cg1) * 1024 + scol;
            float2 xr0 = *(const float2*)&x[idx0];
            float2 xr1 = *(const float2*)&x[idx1];
            float2 v0 = make_float2(acc[mt][nt][0] + bv0 + xr0.x,
                                    acc[mt][nt][1] + bv0 + xr0.y);
            float2 v1 = make_float2(acc[mt][nt][2] + bv1 + xr1.x,
                                    acc[mt][nt][3] + bv1 + xr1.y);
            *(float2*)&out[idx0] = v0;
            *(float2*)&out[idx1] = v1;
        }
    }
}

// ---------------------------------------------------------------------------
extern "C" void kernel_launch(void* const* d_in, const int* in_sizes, int n_in,
                              void* d_out, int out_size) {
    const float* x      = (const float*)d_in[0];
    const float* t_emb  = (const float*)d_in[1];
    const float* c_emb  = (const float*)d_in[2];
    const float* gn_w   = (const float*)d_in[3];
    const float* gn_b   = (const float*)d_in[4];
    const float* proj_w = (const float*)d_in[5];
    const float* proj_b = (const float*)d_in[6];
    const float* qkv_w  = (const float*)d_in[7];
    const float* qkv_b  = (const float*)d_in[8];
    const float* out_w  = (const float*)d_in[9];
    const float* out_b  = (const float*)d_in[10];
    float* out = (float*)d_out;

    k_adaln<<<16, 640>>>(t_emb, c_emb, proj_w, proj_b);
    k_gnstat<<<128, 256>>>(x);
    k_gnapply<<<dim3(32, 16), 256>>>(x, gn_w, gn_b);
    k_qkv<<<dim3(6, 128), 256>>>(qkv_w, qkv_b);
    k_attn<<<dim3(128, 8), 256>>>();
    k_oproj<<<dim3(8, 2, 16), 256>>>(out_w, out_b, x, out);
}